// round 1
// baseline (speedup 1.0000x reference)
#include <cuda_runtime.h>
#include <math.h>

#define BATCH 2
#define MSRC  4096
#define NTGT  8192
#define CF    512
#define NCLS  20
#define OUTC  512
#define H1    128
#define H2    256
#define CIN   532   // CF + NCLS
#define KNN   3

// ---------------- scratch (static device globals; no allocation) ----------------
__device__ float g_sem_hidden[BATCH * MSRC * H1];          // 4 MB
__device__ int   g_knn_idx[BATCH * NTGT * KNN];
__device__ float g_knn_d[BATCH * NTGT * KNN];
__device__ float g_combined[(size_t)BATCH * NTGT * CIN];   // 35 MB
__device__ float g_up_hidden[(size_t)BATCH * NTGT * H2];   // 16 MB

// ---------------- generic tiled GEMM: C = act(A[M,K] @ B[K,N] + bias) ----------
// 64x64 tile, BK=16, 16x16 threads, 4x4 micro-tile per thread.
// Requires M % 64 == 0 (true for all call sites). N, K arbitrary (guarded).
#define BM 64
#define BN 64
#define BK 16

__global__ void gemm_bias_act_kernel(const float* __restrict__ A,
                                     const float* __restrict__ B,
                                     const float* __restrict__ bias,
                                     float* __restrict__ C,
                                     int M, int N, int K, int relu)
{
    __shared__ float As[BK][BM + 1];   // +1 pad: conflict-free transposed store
    __shared__ float Bs[BK][BN];

    const int tx = threadIdx.x;        // 0..15
    const int ty = threadIdx.y;        // 0..15
    const int tid = ty * 16 + tx;

    const int rowBase = blockIdx.y * BM;
    const int colBase = blockIdx.x * BN;

    float acc[4][4];
#pragma unroll
    for (int i = 0; i < 4; i++)
#pragma unroll
        for (int j = 0; j < 4; j++) acc[i][j] = 0.0f;

    const int ar = tid / 16;           // 0..15 (row within tile, strided by 16)
    const int ac = tid % 16;           // 0..15 (k within tile)
    const int bn = tid % 64;           // 0..63 (col within tile)
    const int bk = tid / 64;           // 0..3  (k within tile, strided by 4)

    for (int kt = 0; kt < K; kt += BK) {
        // load A tile (64 x 16), store transposed
#pragma unroll
        for (int j = 0; j < 4; j++) {
            int r  = ar + j * 16;
            int gr = rowBase + r;
            int gc = kt + ac;
            As[ac][r] = (gc < K) ? A[(size_t)gr * K + gc] : 0.0f;
        }
        // load B tile (16 x 64)
#pragma unroll
        for (int j = 0; j < 4; j++) {
            int k  = bk + j * 4;
            int gk = kt + k;
            int gn = colBase + bn;
            Bs[k][bn] = (gk < K && gn < N) ? B[(size_t)gk * N + gn] : 0.0f;
        }
        __syncthreads();

#pragma unroll
        for (int kk = 0; kk < BK; kk++) {
            float a[4], b[4];
#pragma unroll
            for (int i = 0; i < 4; i++) a[i] = As[kk][ty * 4 + i];
#pragma unroll
            for (int j = 0; j < 4; j++) b[j] = Bs[kk][tx * 4 + j];
#pragma unroll
            for (int i = 0; i < 4; i++)
#pragma unroll
                for (int j = 0; j < 4; j++)
                    acc[i][j] = fmaf(a[i], b[j], acc[i][j]);
        }
        __syncthreads();
    }

#pragma unroll
    for (int i = 0; i < 4; i++) {
        int gr = rowBase + ty * 4 + i;
#pragma unroll
        for (int j = 0; j < 4; j++) {
            int gc = colBase + tx * 4 + j;
            if (gc < N) {
                float v = acc[i][j] + bias[gc];
                if (relu) v = fmaxf(v, 0.0f);
                C[(size_t)gr * N + gc] = v;
            }
        }
    }
}

// ---------------- brute-force 3-NN ------------------------------------------
// grid: (NTGT/256, BATCH), block: 256. All 4096 source points cached in smem
// (exactly 48 KB). Each thread owns one target; inner loop reads smem with
// warp-uniform addresses (broadcast, conflict-free).
__global__ void knn_kernel(const float* __restrict__ src,
                           const float* __restrict__ tgt)
{
    __shared__ float sx[MSRC], sy[MSRC], sz[MSRC];
    const int b = blockIdx.y;
    const float* s = src + (size_t)b * MSRC * 3;
    for (int i = threadIdx.x; i < MSRC; i += blockDim.x) {
        sx[i] = s[3 * i + 0];
        sy[i] = s[3 * i + 1];
        sz[i] = s[3 * i + 2];
    }
    __syncthreads();

    const int n = blockIdx.x * blockDim.x + threadIdx.x;
    const float* t = tgt + ((size_t)b * NTGT + n) * 3;
    const float px = t[0], py = t[1], pz = t[2];

    float d0 = 1e30f, d1 = 1e30f, d2 = 1e30f;
    int   i0 = 0,     i1 = 0,     i2 = 0;

    for (int j = 0; j < MSRC; j++) {
        float dx = sx[j] - px;
        float dy = sy[j] - py;
        float dz = sz[j] - pz;
        float d = fmaf(dx, dx, fmaf(dy, dy, dz * dz));
        if (d < d2) {
            if (d < d1) {
                d2 = d1; i2 = i1;
                if (d < d0) { d1 = d0; i1 = i0; d0 = d; i0 = j; }
                else        { d1 = d;  i1 = j; }
            } else {
                d2 = d; i2 = j;
            }
        }
    }
    const size_t base = ((size_t)b * NTGT + n) * KNN;
    g_knn_idx[base + 0] = i0; g_knn_idx[base + 1] = i1; g_knn_idx[base + 2] = i2;
    g_knn_d[base + 0] = sqrtf(d0);
    g_knn_d[base + 1] = sqrtf(d1);
    g_knn_d[base + 2] = sqrtf(d2);
}

// ---------------- gather + inverse-distance fuse + semantic softmax ----------
// one block (128 threads) per target row. Feature rows are 2 KB contiguous ->
// float4 loads are fully coalesced. Warp 0 additionally handles the NC=20
// semantic softmax-mean via shfl reductions.
__global__ void fuse_kernel(const float* __restrict__ feat,
                            const float* __restrict__ sem)
{
    const int row = blockIdx.x;             // 0 .. BATCH*NTGT-1
    const int b = row / NTGT;
    const size_t base = (size_t)row * KNN;

    const int i0 = g_knn_idx[base + 0];
    const int i1 = g_knn_idx[base + 1];
    const int i2 = g_knn_idx[base + 2];
    const float dd0 = g_knn_d[base + 0];
    const float dd1 = g_knn_d[base + 1];
    const float dd2 = g_knn_d[base + 2];

    // softmax(-d)
    const float mn = fminf(dd0, fminf(dd1, dd2));
    const float e0 = expf(mn - dd0);
    const float e1 = expf(mn - dd1);
    const float e2 = expf(mn - dd2);
    const float inv = 1.0f / (e0 + e1 + e2);
    const float w0 = e0 * inv, w1 = e1 * inv, w2 = e2 * inv;

    const int t = threadIdx.x;              // 0..127 -> CF/4 float4 lanes
    const float4* f0 = (const float4*)(feat + ((size_t)(b * MSRC + i0)) * CF);
    const float4* f1 = (const float4*)(feat + ((size_t)(b * MSRC + i1)) * CF);
    const float4* f2 = (const float4*)(feat + ((size_t)(b * MSRC + i2)) * CF);
    float4 a0 = f0[t], a1 = f1[t], a2 = f2[t];
    float4 r;
    r.x = fmaf(w0, a0.x, fmaf(w1, a1.x, w2 * a2.x));
    r.y = fmaf(w0, a0.y, fmaf(w1, a1.y, w2 * a2.y));
    r.z = fmaf(w0, a0.z, fmaf(w1, a1.z, w2 * a2.z));
    r.w = fmaf(w0, a0.w, fmaf(w1, a1.w, w2 * a2.w));
    // combined row base: row * 532 floats (16B aligned since 532 % 4 == 0)
    ((float4*)(g_combined + (size_t)row * CIN))[t] = r;

    if (t < 32) {
        int idx[3] = { i0, i1, i2 };
        float accsem = 0.0f;
#pragma unroll
        for (int k = 0; k < 3; k++) {
            const float* srow = sem + ((size_t)(b * MSRC + idx[k])) * NCLS;
            float v = (t < NCLS) ? srow[t] : -1e30f;
            float m = v;
#pragma unroll
            for (int off = 16; off; off >>= 1)
                m = fmaxf(m, __shfl_xor_sync(0xffffffffu, m, off));
            float e = (t < NCLS) ? expf(v - m) : 0.0f;
            float ssum = e;
#pragma unroll
            for (int off = 16; off; off >>= 1)
                ssum += __shfl_xor_sync(0xffffffffu, ssum, off);
            accsem += e / ssum;
        }
        if (t < NCLS)
            g_combined[(size_t)row * CIN + CF + t] = accsem * (1.0f / 3.0f);
    }
}

// ---------------- launch ------------------------------------------------------
extern "C" void kernel_launch(void* const* d_in, const int* in_sizes, int n_in,
                              void* d_out, int out_size)
{
    const float* src_points   = (const float*)d_in[0];
    const float* tgt_points   = (const float*)d_in[1];
    const float* src_features = (const float*)d_in[2];
    const float* w_sem1 = (const float*)d_in[3];
    const float* b_sem1 = (const float*)d_in[4];
    const float* w_sem2 = (const float*)d_in[5];
    const float* b_sem2 = (const float*)d_in[6];
    const float* w_up1  = (const float*)d_in[7];
    const float* b_up1  = (const float*)d_in[8];
    const float* w_up2  = (const float*)d_in[9];
    const float* b_up2  = (const float*)d_in[10];

    float* out = (float*)d_out;
    float* sem_out = out + (size_t)BATCH * NTGT * OUTC;   // semantic_logits section

    void* p;
    cudaGetSymbolAddress(&p, g_sem_hidden);  float* sem_hidden = (float*)p;
    cudaGetSymbolAddress(&p, g_combined);    float* combined   = (float*)p;
    cudaGetSymbolAddress(&p, g_up_hidden);   float* up_hidden  = (float*)p;

    dim3 blk(16, 16);

    // 1) semantic hidden = relu(src_features @ w_sem1 + b1)   [8192 x 128]
    gemm_bias_act_kernel<<<dim3(H1 / BN, BATCH * MSRC / BM), blk>>>(
        src_features, w_sem1, b_sem1, sem_hidden,
        BATCH * MSRC, H1, CF, 1);

    // 2) semantic logits = hidden @ w_sem2 + b2   [8192 x 20] -> d_out tail
    gemm_bias_act_kernel<<<dim3(1, BATCH * MSRC / BM), blk>>>(
        sem_hidden, w_sem2, b_sem2, sem_out,
        BATCH * MSRC, NCLS, H1, 0);

    // 3) brute-force 3-NN
    knn_kernel<<<dim3(NTGT / 256, BATCH), 256>>>(src_points, tgt_points);

    // 4) gather + fuse -> combined [16384 x 532]
    fuse_kernel<<<BATCH * NTGT, 128>>>(src_features, sem_out);

    // 5) up hidden = relu(combined @ w_up1 + b_up1)   [16384 x 256]
    gemm_bias_act_kernel<<<dim3(H2 / BN, BATCH * NTGT / BM), blk>>>(
        combined, w_up1, b_up1, up_hidden,
        BATCH * NTGT, H2, CIN, 1);

    // 6) out = up_hidden @ w_up2 + b_up2   [16384 x 512]
    gemm_bias_act_kernel<<<dim3(OUTC / BN, BATCH * NTGT / BM), blk>>>(
        up_hidden, w_up2, b_up2, out,
        BATCH * NTGT, OUTC, H2, 0);
}

// round 5
// speedup vs baseline: 1.0050x; 1.0050x over previous
#include <cuda_runtime.h>
#include <math.h>

#define BATCH 2
#define MSRC  4096
#define NTGT  8192
#define CF    512
#define NCLS  20
#define OUTC  512
#define H1    128
#define H2    256
#define CIN   532      // CF + NCLS
#define CINP  544      // padded to multiple of 16 for the guard-free GEMM
#define KNN   3

typedef unsigned long long ull;

// ---------------- scratch (static device globals; no allocation) ----------------
__device__ __align__(256) float g_sem_hidden[BATCH * MSRC * H1];          // 4 MB
__device__ __align__(256) int   g_knn_idx[BATCH * NTGT * KNN];
__device__ __align__(256) float g_knn_d[BATCH * NTGT * KNN];
__device__ __align__(256) float g_combined[(size_t)BATCH * NTGT * CINP];  // ~36 MB
__device__ __align__(256) float g_up_hidden[(size_t)BATCH * NTGT * H2];   // 16 MB
__device__ __align__(256) float g_w_up1_pad[CINP * H2];                   // 544 x 256

// ---------------- packed fp32x2 helpers ----------------------------------------
__device__ __forceinline__ ull pack2(float lo, float hi) {
    ull r;
    asm("mov.b64 %0, {%1, %2};" : "=l"(r) : "f"(lo), "f"(hi));
    return r;
}
__device__ __forceinline__ void unpack2(ull v, float& lo, float& hi) {
    asm("mov.b64 {%0, %1}, %2;" : "=f"(lo), "=f"(hi) : "l"(v));
}
__device__ __forceinline__ void fma2(ull& acc, ull a, ull b) {
    asm("fma.rn.f32x2 %0, %1, %2, %0;" : "+l"(acc) : "l"(a), "l"(b));
}

// ---------------- FFMA2 GEMM: C = act(A[M,K] @ B[K,N] + bias) -------------------
// 128x128 block tile, BK=16, 256 threads, 8x8 per-thread micro-tile computed as
// 8 row-splats x 4 column-pairs with fma.rn.f32x2 (2 MACs / fma slot).
// Requirements: M%128==0, N%128==0, K%16==0, lda%4==0, ldb%4==0.
#define GBM 128
#define GBN 128
#define GBK 16
#define AS_STRIDE 260            // floats per k-row of splatted A (2*128 + pad)
#define AS_STRIDE_U 130          // in ull
#define BS_STRIDE 132            // floats per k-row of B tile

__global__ __launch_bounds__(256, 2)
void gemm_f32x2_kernel(const float* __restrict__ A,
                       const float* __restrict__ B,
                       const float* __restrict__ bias,
                       float* __restrict__ C,
                       int M, int N, int K, int lda, int ldb, int relu)
{
    __shared__ __align__(16) float As2[GBK * AS_STRIDE];   // splatted A: (v,v) pairs
    __shared__ __align__(16) float Bs[GBK * BS_STRIDE];

    const int tid = threadIdx.x;
    const int tx = tid & 15;           // column group 0..15 -> cols tx*8..+7
    const int ty = tid >> 4;           // row group 0..15    -> rows ty*8..+7

    const int rowBase = blockIdx.y * GBM;
    const int colBase = blockIdx.x * GBN;

    ull* As2u = (ull*)As2;

    ull acc[8][4];
#pragma unroll
    for (int i = 0; i < 8; i++)
#pragma unroll
        for (int j = 0; j < 4; j++) acc[i][j] = 0ull;

    for (int kt = 0; kt < K; kt += GBK) {
        // --- load A tile (128 x 16) as float4, store SPLATTED into As2 ---
#pragma unroll
        for (int l = 0; l < 2; l++) {
            int f = tid + l * 256;                 // 0..511 float4 slots
            int row = f >> 2;                      // 0..127
            int kq = f & 3;                        // 0..3 -> k = kq*4..+3
            const float4 v = *(const float4*)(A + (size_t)(rowBase + row) * lda + kt + kq * 4);
            As2u[(kq * 4 + 0) * AS_STRIDE_U + row] = pack2(v.x, v.x);
            As2u[(kq * 4 + 1) * AS_STRIDE_U + row] = pack2(v.y, v.y);
            As2u[(kq * 4 + 2) * AS_STRIDE_U + row] = pack2(v.z, v.z);
            As2u[(kq * 4 + 3) * AS_STRIDE_U + row] = pack2(v.w, v.w);
        }
        // --- load B tile (16 x 128) as float4, direct store ---
#pragma unroll
        for (int l = 0; l < 2; l++) {
            int k = (tid >> 5) + l * 8;            // 0..15
            int c4 = tid & 31;                     // float4 column index
            const float4 v = *(const float4*)(B + (size_t)(kt + k) * ldb + colBase + c4 * 4);
            *(float4*)&Bs[k * BS_STRIDE + c4 * 4] = v;
        }
        __syncthreads();

#pragma unroll
        for (int kk = 0; kk < GBK; kk++) {
            ull aa[8], bb[4];
#pragma unroll
            for (int i = 0; i < 8; i++)
                aa[i] = As2u[kk * AS_STRIDE_U + ty * 8 + i];
#pragma unroll
            for (int j = 0; j < 4; j++)
                bb[j] = *(const ull*)&Bs[kk * BS_STRIDE + tx * 8 + j * 2];
#pragma unroll
            for (int i = 0; i < 8; i++)
#pragma unroll
                for (int j = 0; j < 4; j++)
                    fma2(acc[i][j], aa[i], bb[j]);
        }
        __syncthreads();
    }

    // --- epilogue ---
    const int col0 = colBase + tx * 8;
    float bsv[8];
#pragma unroll
    for (int j = 0; j < 8; j++) bsv[j] = bias[col0 + j];

#pragma unroll
    for (int i = 0; i < 8; i++) {
        const int gr = rowBase + ty * 8 + i;
        float c[8];
#pragma unroll
        for (int j = 0; j < 4; j++) unpack2(acc[i][j], c[2 * j], c[2 * j + 1]);
#pragma unroll
        for (int j = 0; j < 8; j++) {
            c[j] += bsv[j];
            if (relu) c[j] = fmaxf(c[j], 0.0f);
        }
        float4 lo = { c[0], c[1], c[2], c[3] };
        float4 hi = { c[4], c[5], c[6], c[7] };
        *(float4*)(C + (size_t)gr * N + col0) = lo;
        *(float4*)(C + (size_t)gr * N + col0 + 4) = hi;
    }
}

// ---------------- small tiled GEMM (kept for N=20 logits) ----------------------
#define BM 64
#define BN 64
#define BK 16

__global__ void gemm_bias_act_kernel(const float* __restrict__ A,
                                     const float* __restrict__ B,
                                     const float* __restrict__ bias,
                                     float* __restrict__ C,
                                     int M, int N, int K, int relu)
{
    __shared__ float As[BK][BM + 1];
    __shared__ float Bs[BK][BN];

    const int tx = threadIdx.x;
    const int ty = threadIdx.y;
    const int tid = ty * 16 + tx;

    const int rowBase = blockIdx.y * BM;
    const int colBase = blockIdx.x * BN;

    float acc[4][4];
#pragma unroll
    for (int i = 0; i < 4; i++)
#pragma unroll
        for (int j = 0; j < 4; j++) acc[i][j] = 0.0f;

    const int ar = tid / 16;
    const int ac = tid % 16;
    const int bn = tid % 64;
    const int bk = tid / 64;

    for (int kt = 0; kt < K; kt += BK) {
#pragma unroll
        for (int j = 0; j < 4; j++) {
            int r = ar + j * 16;
            int gr = rowBase + r;
            int gc = kt + ac;
            As[ac][r] = (gc < K) ? A[(size_t)gr * K + gc] : 0.0f;
        }
#pragma unroll
        for (int j = 0; j < 4; j++) {
            int k = bk + j * 4;
            int gk = kt + k;
            int gn = colBase + bn;
            Bs[k][bn] = (gk < K && gn < N) ? B[(size_t)gk * N + gn] : 0.0f;
        }
        __syncthreads();

#pragma unroll
        for (int kk = 0; kk < BK; kk++) {
            float a[4], b[4];
#pragma unroll
            for (int i = 0; i < 4; i++) a[i] = As[kk][ty * 4 + i];
#pragma unroll
            for (int j = 0; j < 4; j++) b[j] = Bs[kk][tx * 4 + j];
#pragma unroll
            for (int i = 0; i < 4; i++)
#pragma unroll
                for (int j = 0; j < 4; j++)
                    acc[i][j] = fmaf(a[i], b[j], acc[i][j]);
        }
        __syncthreads();
    }

#pragma unroll
    for (int i = 0; i < 4; i++) {
        int gr = rowBase + ty * 4 + i;
#pragma unroll
        for (int j = 0; j < 4; j++) {
            int gc = colBase + tx * 4 + j;
            if (gc < N) {
                float v = acc[i][j] + bias[gc];
                if (relu) v = fmaxf(v, 0.0f);
                C[(size_t)gr * N + gc] = v;
            }
        }
    }
}

// ---------------- pad w_up1 [532,256] -> [544,256] with zero rows --------------
__global__ void pad_w_up1_kernel(const float* __restrict__ w)
{
    int i = blockIdx.x * 256 + threadIdx.x;
    if (i < CINP * H2) {
        int r = i / H2, c = i % H2;
        g_w_up1_pad[i] = (r < CIN) ? w[r * H2 + c] : 0.0f;
    }
}

// ---------------- brute-force 3-NN ---------------------------------------------
__global__ void knn_kernel(const float* __restrict__ src,
                           const float* __restrict__ tgt)
{
    __shared__ float sx[MSRC], sy[MSRC], sz[MSRC];
    const int b = blockIdx.y;
    const float* s = src + (size_t)b * MSRC * 3;
    for (int i = threadIdx.x; i < MSRC; i += blockDim.x) {
        sx[i] = s[3 * i + 0];
        sy[i] = s[3 * i + 1];
        sz[i] = s[3 * i + 2];
    }
    __syncthreads();

    const int n = blockIdx.x * blockDim.x + threadIdx.x;
    const float* t = tgt + ((size_t)b * NTGT + n) * 3;
    const float px = t[0], py = t[1], pz = t[2];

    float d0 = 1e30f, d1 = 1e30f, d2 = 1e30f;
    int   i0 = 0,     i1 = 0,     i2 = 0;

#pragma unroll 8
    for (int j = 0; j < MSRC; j++) {
        float dx = sx[j] - px;
        float dy = sy[j] - py;
        float dz = sz[j] - pz;
        float d = fmaf(dx, dx, fmaf(dy, dy, dz * dz));
        if (d < d2) {
            if (d < d1) {
                d2 = d1; i2 = i1;
                if (d < d0) { d1 = d0; i1 = i0; d0 = d; i0 = j; }
                else        { d1 = d;  i1 = j; }
            } else {
                d2 = d; i2 = j;
            }
        }
    }
    const size_t base = ((size_t)b * NTGT + n) * KNN;
    g_knn_idx[base + 0] = i0; g_knn_idx[base + 1] = i1; g_knn_idx[base + 2] = i2;
    g_knn_d[base + 0] = sqrtf(d0);
    g_knn_d[base + 1] = sqrtf(d1);
    g_knn_d[base + 2] = sqrtf(d2);
}

// ---------------- gather + fuse + semantic softmax (padded-row output) ----------
__global__ void fuse_kernel(const float* __restrict__ feat,
                            const float* __restrict__ sem)
{
    const int row = blockIdx.x;             // 0 .. BATCH*NTGT-1
    const int b = row / NTGT;
    const size_t base = (size_t)row * KNN;

    const int i0 = g_knn_idx[base + 0];
    const int i1 = g_knn_idx[base + 1];
    const int i2 = g_knn_idx[base + 2];
    const float dd0 = g_knn_d[base + 0];
    const float dd1 = g_knn_d[base + 1];
    const float dd2 = g_knn_d[base + 2];

    const float mn = fminf(dd0, fminf(dd1, dd2));
    const float e0 = expf(mn - dd0);
    const float e1 = expf(mn - dd1);
    const float e2 = expf(mn - dd2);
    const float inv = 1.0f / (e0 + e1 + e2);
    const float w0 = e0 * inv, w1 = e1 * inv, w2 = e2 * inv;

    const int t = threadIdx.x;              // 0..127
    const float4* f0 = (const float4*)(feat + ((size_t)(b * MSRC + i0)) * CF);
    const float4* f1 = (const float4*)(feat + ((size_t)(b * MSRC + i1)) * CF);
    const float4* f2 = (const float4*)(feat + ((size_t)(b * MSRC + i2)) * CF);
    float4 a0 = f0[t], a1 = f1[t], a2 = f2[t];
    float4 r;
    r.x = fmaf(w0, a0.x, fmaf(w1, a1.x, w2 * a2.x));
    r.y = fmaf(w0, a0.y, fmaf(w1, a1.y, w2 * a2.y));
    r.z = fmaf(w0, a0.z, fmaf(w1, a1.z, w2 * a2.z));
    r.w = fmaf(w0, a0.w, fmaf(w1, a1.w, w2 * a2.w));
    float* crow = g_combined + (size_t)row * CINP;
    ((float4*)crow)[t] = r;

    // zero the pad columns 532..543 (float4 slots 133..135)
    if (t >= 125) {
        float4 z = { 0.f, 0.f, 0.f, 0.f };
        ((float4*)crow)[t + 8] = z;         // 133,134,135
    }

    if (t < 32) {
        int idx[3] = { i0, i1, i2 };
        float accsem = 0.0f;
#pragma unroll
        for (int k = 0; k < 3; k++) {
            const float* srow = sem + ((size_t)(b * MSRC + idx[k])) * NCLS;
            float v = (t < NCLS) ? srow[t] : -1e30f;
            float m = v;
#pragma unroll
            for (int off = 16; off; off >>= 1)
                m = fmaxf(m, __shfl_xor_sync(0xffffffffu, m, off));
            float e = (t < NCLS) ? expf(v - m) : 0.0f;
            float ssum = e;
#pragma unroll
            for (int off = 16; off; off >>= 1)
                ssum += __shfl_xor_sync(0xffffffffu, ssum, off);
            accsem += e / ssum;
        }
        if (t < NCLS)
            crow[CF + t] = accsem * (1.0f / 3.0f);
    }
}

// ---------------- launch --------------------------------------------------------
extern "C" void kernel_launch(void* const* d_in, const int* in_sizes, int n_in,
                              void* d_out, int out_size)
{
    const float* src_points   = (const float*)d_in[0];
    const float* tgt_points   = (const float*)d_in[1];
    const float* src_features = (const float*)d_in[2];
    const float* w_sem1 = (const float*)d_in[3];
    const float* b_sem1 = (const float*)d_in[4];
    const float* w_sem2 = (const float*)d_in[5];
    const float* b_sem2 = (const float*)d_in[6];
    const float* w_up1  = (const float*)d_in[7];
    const float* b_up1  = (const float*)d_in[8];
    const float* w_up2  = (const float*)d_in[9];
    const float* b_up2  = (const float*)d_in[10];

    float* out = (float*)d_out;
    float* sem_out = out + (size_t)BATCH * NTGT * OUTC;

    void* p;
    cudaGetSymbolAddress(&p, g_sem_hidden);  float* sem_hidden = (float*)p;
    cudaGetSymbolAddress(&p, g_combined);    float* combined   = (float*)p;
    cudaGetSymbolAddress(&p, g_up_hidden);   float* up_hidden  = (float*)p;
    cudaGetSymbolAddress(&p, g_w_up1_pad);   float* w_up1_pad  = (float*)p;

    // 0) pad w_up1 to 544 rows
    pad_w_up1_kernel<<<(CINP * H2 + 255) / 256, 256>>>(w_up1);

    // 1) semantic hidden = relu(src_features @ w_sem1 + b1)   [8192 x 128]
    gemm_f32x2_kernel<<<dim3(H1 / GBN, BATCH * MSRC / GBM), 256>>>(
        src_features, w_sem1, b_sem1, sem_hidden,
        BATCH * MSRC, H1, CF, CF, H1, 1);

    // 2) semantic logits = hidden @ w_sem2 + b2   [8192 x 20] -> d_out tail
    gemm_bias_act_kernel<<<dim3(1, BATCH * MSRC / BM), dim3(16, 16)>>>(
        sem_hidden, w_sem2, b_sem2, sem_out,
        BATCH * MSRC, NCLS, H1, 0);

    // 3) brute-force 3-NN
    knn_kernel<<<dim3(NTGT / 128, BATCH), 128>>>(src_points, tgt_points);

    // 4) gather + fuse -> combined [16384 x 544] (cols 532..543 zero)
    fuse_kernel<<<BATCH * NTGT, 128>>>(src_features, sem_out);

    // 5) up hidden = relu(combined @ w_up1_pad + b_up1)   [16384 x 256], K=544
    gemm_f32x2_kernel<<<dim3(H2 / GBN, BATCH * NTGT / GBM), 256>>>(
        combined, w_up1_pad, b_up1, up_hidden,
        BATCH * NTGT, H2, CINP, CINP, H2, 1);

    // 6) out = up_hidden @ w_up2 + b_up2   [16384 x 512], K=256
    gemm_f32x2_kernel<<<dim3(OUTC / GBN, BATCH * NTGT / GBM), 256>>>(
        up_hidden, w_up2, b_up2, out,
        BATCH * NTGT, OUTC, H2, H2, OUTC, 0);
}

// round 7
// speedup vs baseline: 1.1659x; 1.1601x over previous
#include <cuda_runtime.h>
#include <math.h>

#define BATCH 2
#define MSRC  4096
#define NTGT  8192
#define CF    512
#define NCLS  20
#define OUTC  512
#define H1    128
#define H2    256
#define CIN   532      // CF + NCLS
#define CINP  544      // padded to multiple of 16 for the guard-free GEMM
#define KNN   3

typedef unsigned long long ull;

// ---------------- scratch (static device globals; no allocation) ----------------
__device__ __align__(256) float g_sem_hidden[BATCH * MSRC * H1];          // 4 MB
__device__ __align__(256) int   g_knn_idx[BATCH * NTGT * KNN];
__device__ __align__(256) float g_knn_d[BATCH * NTGT * KNN];
__device__ __align__(256) float g_combined[(size_t)BATCH * NTGT * CINP];  // ~36 MB
__device__ __align__(256) float g_up_hidden[(size_t)BATCH * NTGT * H2];   // 16 MB
__device__ __align__(256) float g_w_up1_pad[CINP * H2];                   // 544 x 256

// ---------------- packed fp32x2 helpers ----------------------------------------
__device__ __forceinline__ ull pack2(float lo, float hi) {
    ull r;
    asm("mov.b64 %0, {%1, %2};" : "=l"(r) : "f"(lo), "f"(hi));
    return r;
}
__device__ __forceinline__ void unpack2(ull v, float& lo, float& hi) {
    asm("mov.b64 {%0, %1}, %2;" : "=f"(lo), "=f"(hi) : "l"(v));
}
__device__ __forceinline__ void fma2(ull& acc, ull a, ull b) {
    asm("fma.rn.f32x2 %0, %1, %2, %0;" : "+l"(acc) : "l"(a), "l"(b));
}

// ---------------- FFMA2 GEMM, double-buffered -----------------------------------
// 128x128 block tile, BK=16, 256 threads, 8x8 per-thread micro-tile via
// fma.rn.f32x2 (2 MACs / fma slot). Double-buffered smem, reg prefetch,
// ONE __syncthreads per K-tile.
// Requirements: M%128==0, N%128==0, K%16==0.
#define GBM 128
#define GBN 128
#define GBK 16
#define AS_STRIDE 260            // floats per k-row of splatted A (2*128 + pad)
#define AS_STRIDE_U 130          // in ull
#define BS_STRIDE 132            // floats per k-row of B tile

__global__ __launch_bounds__(256, 2)
void gemm_f32x2_kernel(const float* __restrict__ A,
                       const float* __restrict__ B,
                       const float* __restrict__ bias,
                       float* __restrict__ C,
                       int M, int N, int K, int lda, int ldb, int relu)
{
    __shared__ __align__(16) float As2[2][GBK * AS_STRIDE];
    __shared__ __align__(16) float Bs[2][GBK * BS_STRIDE];

    const int tid = threadIdx.x;
    const int tx = tid & 15;           // column group 0..15 -> cols tx*8..+7
    const int ty = tid >> 4;           // row group 0..15    -> rows ty*8..+7

    const int rowBase = blockIdx.y * GBM;
    const int colBase = blockIdx.x * GBN;

    // invariant load indices
    const int rA0 = tid >> 2, kqA = tid & 3;     // A slot 0: row, k-quad
    const int rA1 = (tid + 256) >> 2;            // A slot 1 (same k-quad)
    const int kB0 = tid >> 5, kB1 = kB0 + 8, c4 = tid & 31;

    const float* Ab0 = A + (size_t)(rowBase + rA0) * lda + kqA * 4;
    const float* Ab1 = A + (size_t)(rowBase + rA1) * lda + kqA * 4;
    const float* Bb0 = B + (size_t)kB0 * ldb + colBase + c4 * 4;
    const float* Bb1 = B + (size_t)kB1 * ldb + colBase + c4 * 4;

    ull acc[8][4];
#pragma unroll
    for (int i = 0; i < 8; i++)
#pragma unroll
        for (int j = 0; j < 4; j++) acc[i][j] = 0ull;

    float4 aR0, aR1, bR0, bR1;

    // prologue: load tile 0 -> regs -> smem buf 0
    aR0 = *(const float4*)(Ab0);
    aR1 = *(const float4*)(Ab1);
    bR0 = *(const float4*)(Bb0);
    bR1 = *(const float4*)(Bb1);
    {
        ull* Au = (ull*)As2[0];
        Au[(kqA * 4 + 0) * AS_STRIDE_U + rA0] = pack2(aR0.x, aR0.x);
        Au[(kqA * 4 + 1) * AS_STRIDE_U + rA0] = pack2(aR0.y, aR0.y);
        Au[(kqA * 4 + 2) * AS_STRIDE_U + rA0] = pack2(aR0.z, aR0.z);
        Au[(kqA * 4 + 3) * AS_STRIDE_U + rA0] = pack2(aR0.w, aR0.w);
        Au[(kqA * 4 + 0) * AS_STRIDE_U + rA1] = pack2(aR1.x, aR1.x);
        Au[(kqA * 4 + 1) * AS_STRIDE_U + rA1] = pack2(aR1.y, aR1.y);
        Au[(kqA * 4 + 2) * AS_STRIDE_U + rA1] = pack2(aR1.z, aR1.z);
        Au[(kqA * 4 + 3) * AS_STRIDE_U + rA1] = pack2(aR1.w, aR1.w);
        *(float4*)&Bs[0][kB0 * BS_STRIDE + c4 * 4] = bR0;
        *(float4*)&Bs[0][kB1 * BS_STRIDE + c4 * 4] = bR1;
    }
    __syncthreads();

    int p = 0;
    for (int kt = 0; kt < K; kt += GBK) {
        const int ktn = kt + GBK;
        const bool more = (ktn < K);
        if (more) {
            aR0 = *(const float4*)(Ab0 + ktn);
            aR1 = *(const float4*)(Ab1 + ktn);
            bR0 = *(const float4*)(Bb0 + (size_t)ktn * ldb);
            bR1 = *(const float4*)(Bb1 + (size_t)ktn * ldb);
        }

        const ull* Au = (const ull*)As2[p];
        const float* Bp = Bs[p];
#pragma unroll
        for (int kk = 0; kk < GBK; kk++) {
            ull aa[8], bb[4];
#pragma unroll
            for (int i = 0; i < 8; i++)
                aa[i] = Au[kk * AS_STRIDE_U + ty * 8 + i];
#pragma unroll
            for (int j = 0; j < 4; j++)
                bb[j] = *(const ull*)&Bp[kk * BS_STRIDE + tx * 8 + j * 2];
#pragma unroll
            for (int i = 0; i < 8; i++)
#pragma unroll
                for (int j = 0; j < 4; j++)
                    fma2(acc[i][j], aa[i], bb[j]);
        }

        if (more) {
            ull* Aw = (ull*)As2[p ^ 1];
            Aw[(kqA * 4 + 0) * AS_STRIDE_U + rA0] = pack2(aR0.x, aR0.x);
            Aw[(kqA * 4 + 1) * AS_STRIDE_U + rA0] = pack2(aR0.y, aR0.y);
            Aw[(kqA * 4 + 2) * AS_STRIDE_U + rA0] = pack2(aR0.z, aR0.z);
            Aw[(kqA * 4 + 3) * AS_STRIDE_U + rA0] = pack2(aR0.w, aR0.w);
            Aw[(kqA * 4 + 0) * AS_STRIDE_U + rA1] = pack2(aR1.x, aR1.x);
            Aw[(kqA * 4 + 1) * AS_STRIDE_U + rA1] = pack2(aR1.y, aR1.y);
            Aw[(kqA * 4 + 2) * AS_STRIDE_U + rA1] = pack2(aR1.z, aR1.z);
            Aw[(kqA * 4 + 3) * AS_STRIDE_U + rA1] = pack2(aR1.w, aR1.w);
            *(float4*)&Bs[p ^ 1][kB0 * BS_STRIDE + c4 * 4] = bR0;
            *(float4*)&Bs[p ^ 1][kB1 * BS_STRIDE + c4 * 4] = bR1;
        }
        __syncthreads();
        p ^= 1;
    }

    // --- epilogue ---
    const int col0 = colBase + tx * 8;
    float bsv[8];
#pragma unroll
    for (int j = 0; j < 8; j++) bsv[j] = bias[col0 + j];

#pragma unroll
    for (int i = 0; i < 8; i++) {
        const int gr = rowBase + ty * 8 + i;
        float c[8];
#pragma unroll
        for (int j = 0; j < 4; j++) unpack2(acc[i][j], c[2 * j], c[2 * j + 1]);
#pragma unroll
        for (int j = 0; j < 8; j++) {
            c[j] += bsv[j];
            if (relu) c[j] = fmaxf(c[j], 0.0f);
        }
        float4 lo = { c[0], c[1], c[2], c[3] };
        float4 hi = { c[4], c[5], c[6], c[7] };
        *(float4*)(C + (size_t)gr * N + col0) = lo;
        *(float4*)(C + (size_t)gr * N + col0 + 4) = hi;
    }
}

// ---------------- small tiled GEMM (kept for N=20 logits) ----------------------
#define BM 64
#define BN 64
#define BK 16

__global__ void gemm_bias_act_kernel(const float* __restrict__ A,
                                     const float* __restrict__ B,
                                     const float* __restrict__ bias,
                                     float* __restrict__ C,
                                     int M, int N, int K, int relu)
{
    __shared__ float As[BK][BM + 1];
    __shared__ float Bs[BK][BN];

    const int tx = threadIdx.x;
    const int ty = threadIdx.y;
    const int tid = ty * 16 + tx;

    const int rowBase = blockIdx.y * BM;
    const int colBase = blockIdx.x * BN;

    float acc[4][4];
#pragma unroll
    for (int i = 0; i < 4; i++)
#pragma unroll
        for (int j = 0; j < 4; j++) acc[i][j] = 0.0f;

    const int ar = tid / 16;
    const int ac = tid % 16;
    const int bn = tid % 64;
    const int bk = tid / 64;

    for (int kt = 0; kt < K; kt += BK) {
#pragma unroll
        for (int j = 0; j < 4; j++) {
            int r = ar + j * 16;
            int gr = rowBase + r;
            int gc = kt + ac;
            As[ac][r] = (gc < K) ? A[(size_t)gr * K + gc] : 0.0f;
        }
#pragma unroll
        for (int j = 0; j < 4; j++) {
            int k = bk + j * 4;
            int gk = kt + k;
            int gn = colBase + bn;
            Bs[k][bn] = (gk < K && gn < N) ? B[(size_t)gk * N + gn] : 0.0f;
        }
        __syncthreads();

#pragma unroll
        for (int kk = 0; kk < BK; kk++) {
            float a[4], b[4];
#pragma unroll
            for (int i = 0; i < 4; i++) a[i] = As[kk][ty * 4 + i];
#pragma unroll
            for (int j = 0; j < 4; j++) b[j] = Bs[kk][tx * 4 + j];
#pragma unroll
            for (int i = 0; i < 4; i++)
#pragma unroll
                for (int j = 0; j < 4; j++)
                    acc[i][j] = fmaf(a[i], b[j], acc[i][j]);
        }
        __syncthreads();
    }

#pragma unroll
    for (int i = 0; i < 4; i++) {
        int gr = rowBase + ty * 4 + i;
#pragma unroll
        for (int j = 0; j < 4; j++) {
            int gc = colBase + tx * 4 + j;
            if (gc < N) {
                float v = acc[i][j] + bias[gc];
                if (relu) v = fmaxf(v, 0.0f);
                C[(size_t)gr * N + gc] = v;
            }
        }
    }
}

// ---------------- pad w_up1 [532,256] -> [544,256] with zero rows --------------
__global__ void pad_w_up1_kernel(const float* __restrict__ w)
{
    int i = blockIdx.x * 256 + threadIdx.x;
    if (i < CINP * H2) {
        int r = i / H2, c = i % H2;
        g_w_up1_pad[i] = (r < CIN) ? w[r * H2 + c] : 0.0f;
    }
}

// ---------------- warp-cooperative 3-NN ----------------------------------------
// 256 threads = 8 warps; each warp owns 4 targets; lanes split the 4096 source
// points (128 each, lane-strided). Ranking key r = |s|^2 - 2<s,t> (reference's
// own expansion, monotone in distance for fixed t). Cross-lane top-3 merge via
// packed (ordered-float<<32 | idx) u64 keys -> deterministic, lowest idx wins.
#define KNN_WARPS 8
#define KNN_TPW   4
#define KNN_TGTPB (KNN_WARPS * KNN_TPW)   // 32 targets per block

__device__ __forceinline__ ull knn_packkey(float r, int j) {
    unsigned u = __float_as_uint(r);
    u = (u & 0x80000000u) ? ~u : (u | 0x80000000u);
    return ((ull)u << 32) | (unsigned)j;
}
__device__ __forceinline__ float knn_unpackr(ull k) {
    unsigned u = (unsigned)(k >> 32);
    u = (u & 0x80000000u) ? (u & 0x7fffffffu) : ~u;
    return __uint_as_float(u);
}
__device__ __forceinline__ void knn_insert(ull& k0, ull& k1, ull& k2, ull k) {
    if (k < k2) {
        if (k < k1) {
            k2 = k1;
            if (k < k0) { k1 = k0; k0 = k; }
            else        { k1 = k; }
        } else {
            k2 = k;
        }
    }
}

__global__ __launch_bounds__(256)
void knn_kernel(const float* __restrict__ src,
                const float* __restrict__ tgt)
{
    __shared__ float sx[MSRC], sy[MSRC], sz[MSRC];   // 48 KB
    const int b = blockIdx.y;
    const float* s = src + (size_t)b * MSRC * 3;
    for (int i = threadIdx.x; i < MSRC; i += 256) {
        sx[i] = s[3 * i + 0];
        sy[i] = s[3 * i + 1];
        sz[i] = s[3 * i + 2];
    }
    __syncthreads();

    const int warp = threadIdx.x >> 5;
    const int lane = threadIdx.x & 31;
    const int tbase = blockIdx.x * KNN_TGTPB + warp * KNN_TPW;

    float px[KNN_TPW], py[KNN_TPW], pz[KNN_TPW], pn[KNN_TPW];
#pragma unroll
    for (int t = 0; t < KNN_TPW; t++) {
        const float* tp = tgt + ((size_t)b * NTGT + tbase + t) * 3;
        px[t] = tp[0]; py[t] = tp[1]; pz[t] = tp[2];
        pn[t] = fmaf(px[t], px[t], fmaf(py[t], py[t], pz[t] * pz[t]));
    }

    float r0[KNN_TPW], r1[KNN_TPW], r2[KNN_TPW];
    int   j0[KNN_TPW], j1[KNN_TPW], j2[KNN_TPW];
#pragma unroll
    for (int t = 0; t < KNN_TPW; t++) {
        r0[t] = r1[t] = r2[t] = 1e30f;
        j0[t] = j1[t] = j2[t] = 0;
    }

    for (int j = lane; j < MSRC; j += 32) {
        const float x = sx[j], y = sy[j], z = sz[j];
        const float s2 = fmaf(x, x, fmaf(y, y, z * z));
        const float xm2 = -2.0f * x, ym2 = -2.0f * y, zm2 = -2.0f * z;
#pragma unroll
        for (int t = 0; t < KNN_TPW; t++) {
            const float r = fmaf(xm2, px[t], fmaf(ym2, py[t], fmaf(zm2, pz[t], s2)));
            if (r < r2[t]) {
                if (r < r1[t]) {
                    r2[t] = r1[t]; j2[t] = j1[t];
                    if (r < r0[t]) { r1[t] = r0[t]; j1[t] = j0[t]; r0[t] = r; j0[t] = j; }
                    else           { r1[t] = r; j1[t] = j; }
                } else {
                    r2[t] = r; j2[t] = j;
                }
            }
        }
    }

#pragma unroll
    for (int t = 0; t < KNN_TPW; t++) {
        ull k0 = knn_packkey(r0[t], j0[t]);
        ull k1 = knn_packkey(r1[t], j1[t]);
        ull k2 = knn_packkey(r2[t], j2[t]);
#pragma unroll
        for (int off = 16; off; off >>= 1) {
            ull o0 = __shfl_xor_sync(0xffffffffu, k0, off);
            ull o1 = __shfl_xor_sync(0xffffffffu, k1, off);
            ull o2 = __shfl_xor_sync(0xffffffffu, k2, off);
            knn_insert(k0, k1, k2, o0);
            knn_insert(k0, k1, k2, o1);
            knn_insert(k0, k1, k2, o2);
        }
        if (lane == 0) {
            const size_t base = ((size_t)b * NTGT + tbase + t) * KNN;
            g_knn_idx[base + 0] = (int)(unsigned)k0;
            g_knn_idx[base + 1] = (int)(unsigned)k1;
            g_knn_idx[base + 2] = (int)(unsigned)k2;
            g_knn_d[base + 0] = sqrtf(fmaxf(knn_unpackr(k0) + pn[t], 0.0f));
            g_knn_d[base + 1] = sqrtf(fmaxf(knn_unpackr(k1) + pn[t], 0.0f));
            g_knn_d[base + 2] = sqrtf(fmaxf(knn_unpackr(k2) + pn[t], 0.0f));
        }
    }
}

// ---------------- gather + fuse + semantic softmax (padded-row output) ----------
__global__ void fuse_kernel(const float* __restrict__ feat,
                            const float* __restrict__ sem)
{
    const int row = blockIdx.x;             // 0 .. BATCH*NTGT-1
    const int b = row / NTGT;
    const size_t base = (size_t)row * KNN;

    const int i0 = g_knn_idx[base + 0];
    const int i1 = g_knn_idx[base + 1];
    const int i2 = g_knn_idx[base + 2];
    const float dd0 = g_knn_d[base + 0];
    const float dd1 = g_knn_d[base + 1];
    const float dd2 = g_knn_d[base + 2];

    const float mn = fminf(dd0, fminf(dd1, dd2));
    const float e0 = expf(mn - dd0);
    const float e1 = expf(mn - dd1);
    const float e2 = expf(mn - dd2);
    const float inv = 1.0f / (e0 + e1 + e2);
    const float w0 = e0 * inv, w1 = e1 * inv, w2 = e2 * inv;

    const int t = threadIdx.x;              // 0..127
    const float4* f0 = (const float4*)(feat + ((size_t)(b * MSRC + i0)) * CF);
    const float4* f1 = (const float4*)(feat + ((size_t)(b * MSRC + i1)) * CF);
    const float4* f2 = (const float4*)(feat + ((size_t)(b * MSRC + i2)) * CF);
    float4 a0 = f0[t], a1 = f1[t], a2 = f2[t];
    float4 r;
    r.x = fmaf(w0, a0.x, fmaf(w1, a1.x, w2 * a2.x));
    r.y = fmaf(w0, a0.y, fmaf(w1, a1.y, w2 * a2.y));
    r.z = fmaf(w0, a0.z, fmaf(w1, a1.z, w2 * a2.z));
    r.w = fmaf(w0, a0.w, fmaf(w1, a1.w, w2 * a2.w));
    float* crow = g_combined + (size_t)row * CINP;
    ((float4*)crow)[t] = r;

    // zero the pad columns 532..543 (float4 slots 133..135)
    if (t >= 125) {
        float4 z = { 0.f, 0.f, 0.f, 0.f };
        ((float4*)crow)[t + 8] = z;         // 133,134,135
    }

    if (t < 32) {
        int idx[3] = { i0, i1, i2 };
        float accsem = 0.0f;
#pragma unroll
        for (int k = 0; k < 3; k++) {
            const float* srow = sem + ((size_t)(b * MSRC + idx[k])) * NCLS;
            float v = (t < NCLS) ? srow[t] : -1e30f;
            float m = v;
#pragma unroll
            for (int off = 16; off; off >>= 1)
                m = fmaxf(m, __shfl_xor_sync(0xffffffffu, m, off));
            float e = (t < NCLS) ? expf(v - m) : 0.0f;
            float ssum = e;
#pragma unroll
            for (int off = 16; off; off >>= 1)
                ssum += __shfl_xor_sync(0xffffffffu, ssum, off);
            accsem += e / ssum;
        }
        if (t < NCLS)
            crow[CF + t] = accsem * (1.0f / 3.0f);
    }
}

// ---------------- launch --------------------------------------------------------
extern "C" void kernel_launch(void* const* d_in, const int* in_sizes, int n_in,
                              void* d_out, int out_size)
{
    const float* src_points   = (const float*)d_in[0];
    const float* tgt_points   = (const float*)d_in[1];
    const float* src_features = (const float*)d_in[2];
    const float* w_sem1 = (const float*)d_in[3];
    const float* b_sem1 = (const float*)d_in[4];
    const float* w_sem2 = (const float*)d_in[5];
    const float* b_sem2 = (const float*)d_in[6];
    const float* w_up1  = (const float*)d_in[7];
    const float* b_up1  = (const float*)d_in[8];
    const float* w_up2  = (const float*)d_in[9];
    const float* b_up2  = (const float*)d_in[10];

    float* out = (float*)d_out;
    float* sem_out = out + (size_t)BATCH * NTGT * OUTC;

    void* p;
    cudaGetSymbolAddress(&p, g_sem_hidden);  float* sem_hidden = (float*)p;
    cudaGetSymbolAddress(&p, g_combined);    float* combined   = (float*)p;
    cudaGetSymbolAddress(&p, g_up_hidden);   float* up_hidden  = (float*)p;
    cudaGetSymbolAddress(&p, g_w_up1_pad);   float* w_up1_pad  = (float*)p;

    // 0) pad w_up1 to 544 rows
    pad_w_up1_kernel<<<(CINP * H2 + 255) / 256, 256>>>(w_up1);

    // 1) semantic hidden = relu(src_features @ w_sem1 + b1)   [8192 x 128]
    gemm_f32x2_kernel<<<dim3(H1 / GBN, BATCH * MSRC / GBM), 256>>>(
        src_features, w_sem1, b_sem1, sem_hidden,
        BATCH * MSRC, H1, CF, CF, H1, 1);

    // 2) semantic logits = hidden @ w_sem2 + b2   [8192 x 20] -> d_out tail
    gemm_bias_act_kernel<<<dim3(1, BATCH * MSRC / BM), dim3(16, 16)>>>(
        sem_hidden, w_sem2, b_sem2, sem_out,
        BATCH * MSRC, NCLS, H1, 0);

    // 3) warp-cooperative 3-NN
    knn_kernel<<<dim3(NTGT / KNN_TGTPB, BATCH), 256>>>(src_points, tgt_points);

    // 4) gather + fuse -> combined [16384 x 544] (cols 532..543 zero)
    fuse_kernel<<<BATCH * NTGT, 128>>>(src_features, sem_out);

    // 5) up hidden = relu(combined @ w_up1_pad + b_up1)   [16384 x 256], K=544
    gemm_f32x2_kernel<<<dim3(H2 / GBN, BATCH * NTGT / GBM), 256>>>(
        combined, w_up1_pad, b_up1, up_hidden,
        BATCH * NTGT, H2, CINP, CINP, H2, 1);

    // 6) out = up_hidden @ w_up2 + b_up2   [16384 x 512], K=256
    gemm_f32x2_kernel<<<dim3(OUTC / GBN, BATCH * NTGT / GBM), 256>>>(
        up_hidden, w_up2, b_up2, out,
        BATCH * NTGT, OUTC, H2, H2, OUTC, 0);
}

// round 9
// speedup vs baseline: 1.6960x; 1.4547x over previous
#include <cuda_runtime.h>
#include <cuda_bf16.h>
#include <math.h>
#include <cstdint>

#define BATCH 2
#define MSRC  4096
#define NTGT  8192
#define CF    512
#define NCLS  20
#define OUTC  512
#define H1    128
#define H2    256
#define CIN   532
#define KNN   3

// split-K3 sizes (A' = [hi|hi|lo], B' = [hi|lo|hi], zero-padded)
#define K3_SEM  1536          // 3*512
#define KP_UP1  544           // 532 padded to 544
#define K3_UP1  1664          // 3*544=1632 -> pad to 1664
#define K3_UP2  768           // 3*256

typedef unsigned long long ull;

// ---------------- scratch (static device globals; no allocation) ----------------
__device__ __align__(256) float         g_sem_hidden[BATCH * MSRC * H1];
__device__ __align__(256) int           g_knn_idx[BATCH * NTGT * KNN];
__device__ __align__(256) float         g_knn_d[BATCH * NTGT * KNN];
__device__ __align__(256) __nv_bfloat16 g_a_sem[(size_t)BATCH * MSRC * K3_SEM];
__device__ __align__(256) __nv_bfloat16 g_b_sem1[H1 * K3_SEM];
__device__ __align__(256) __nv_bfloat16 g_a_up1[(size_t)BATCH * NTGT * K3_UP1];
__device__ __align__(256) __nv_bfloat16 g_b_up1[H2 * K3_UP1];
__device__ __align__(256) __nv_bfloat16 g_a_up2[(size_t)BATCH * NTGT * K3_UP2];
__device__ __align__(256) __nv_bfloat16 g_b_up2[OUTC * K3_UP2];

// ---------------- helpers -------------------------------------------------------
__device__ __forceinline__ void bf16_split(float v, __nv_bfloat16& h, __nv_bfloat16& l) {
    h = __float2bfloat16(v);
    l = __float2bfloat16(v - __bfloat162float(h));
}
__device__ __forceinline__ unsigned bf16x2_u32(__nv_bfloat16 a, __nv_bfloat16 b) {
    __nv_bfloat162 t; t.x = a; t.y = b;
    return *(unsigned*)&t;
}
__device__ __forceinline__ void mma_bf16(float& d0, float& d1, float& d2, float& d3,
                                         uint32_t a0, uint32_t a1, uint32_t a2, uint32_t a3,
                                         uint32_t b0, uint32_t b1) {
    asm volatile(
        "mma.sync.aligned.m16n8k16.row.col.f32.bf16.bf16.f32 "
        "{%0,%1,%2,%3}, {%4,%5,%6,%7}, {%8,%9}, {%0,%1,%2,%3};"
        : "+f"(d0), "+f"(d1), "+f"(d2), "+f"(d3)
        : "r"(a0), "r"(a1), "r"(a2), "r"(a3), "r"(b0), "r"(b1));
}

// ================= mma.sync split-bf16 GEMM =====================================
// D[M x N] = A'[M x K3] @ B'[N x K3]^T (+bias, act). fp32 accum.
// mode 0: write fp32 C.  mode 1: write split bf16 [M][3N] as (h | h | l).
// Block: 128x128 tile, 256 thr = 8 warps (4x2), warp tile 32x64, BK=32,
// double-buffered smem; padded stride 20 words -> conflict-free fragment LDS.
#define SSTR 20                   // words per row (32 bf16 = 16 words + 4 pad)

__global__ __launch_bounds__(256)
void gemm_mma_kernel(const __nv_bfloat16* __restrict__ Ap,
                     const __nv_bfloat16* __restrict__ Bp,
                     const float* __restrict__ bias,
                     float* __restrict__ Cf,
                     __nv_bfloat16* __restrict__ Csp,
                     int N, int K3, int relu, int mode)
{
    __shared__ uint32_t sA[2][128 * SSTR];
    __shared__ uint32_t sB[2][128 * SSTR];

    const int tid = threadIdx.x;
    const int wid = tid >> 5;
    const int lane = tid & 31;
    const int g = lane >> 2;           // group row 0..7
    const int t = lane & 3;            // 0..3

    const int warp_m = wid & 3;        // 0..3 -> rows warp_m*32
    const int warp_n = wid >> 2;       // 0..1 -> cols warp_n*64

    const int rowBase = blockIdx.x * 128;
    const int colBase = blockIdx.y * 128;

    // global->smem copy indices: thread handles segs f=tid, tid+256 (row=f>>2, seg=f&3)
    const int cr0 = tid >> 2, cs0 = tid & 3;
    const int cr1 = (tid + 256) >> 2;
    const size_t krow = (size_t)K3 * 2;          // bytes per row of A'/B'

    const char* Agp = (const char*)Ap + (size_t)(rowBase + cr0) * krow + cs0 * 16;
    const char* Agp1 = (const char*)Ap + (size_t)(rowBase + cr1) * krow + cs0 * 16;
    const char* Bgp = (const char*)Bp + (size_t)(colBase + cr0) * krow + cs0 * 16;
    const char* Bgp1 = (const char*)Bp + (size_t)(colBase + cr1) * krow + cs0 * 16;

    float acc[2][8][4];
#pragma unroll
    for (int i = 0; i < 2; i++)
#pragma unroll
        for (int j = 0; j < 8; j++)
#pragma unroll
            for (int q = 0; q < 4; q++) acc[i][j][q] = 0.0f;

    const int chunks = K3 >> 5;        // BK = 32

    // prologue: chunk 0 -> buf 0
    {
        uint4 a0 = *(const uint4*)(Agp);
        uint4 a1 = *(const uint4*)(Agp1);
        uint4 b0 = *(const uint4*)(Bgp);
        uint4 b1 = *(const uint4*)(Bgp1);
        *(uint4*)&sA[0][cr0 * SSTR + cs0 * 4] = a0;
        *(uint4*)&sA[0][cr1 * SSTR + cs0 * 4] = a1;
        *(uint4*)&sB[0][cr0 * SSTR + cs0 * 4] = b0;
        *(uint4*)&sB[0][cr1 * SSTR + cs0 * 4] = b1;
    }
    __syncthreads();

    int p = 0;
    for (int ch = 0; ch < chunks; ch++) {
        uint4 pa0, pa1, pb0, pb1;
        const bool more = (ch + 1 < chunks);
        if (more) {
            const size_t off = (size_t)(ch + 1) * 64;   // 32 bf16 = 64 B
            pa0 = *(const uint4*)(Agp + off);
            pa1 = *(const uint4*)(Agp1 + off);
            pb0 = *(const uint4*)(Bgp + off);
            pb1 = *(const uint4*)(Bgp1 + off);
        }

        const uint32_t* A_ = sA[p];
        const uint32_t* B_ = sB[p];
#pragma unroll
        for (int s = 0; s < 2; s++) {                  // two k16 steps
            const int w0 = s * 8 + t;
            uint32_t afr[2][4];
#pragma unroll
            for (int mt = 0; mt < 2; mt++) {
                const int r = warp_m * 32 + mt * 16 + g;
                afr[mt][0] = A_[r * SSTR + w0];
                afr[mt][1] = A_[(r + 8) * SSTR + w0];
                afr[mt][2] = A_[r * SSTR + w0 + 4];
                afr[mt][3] = A_[(r + 8) * SSTR + w0 + 4];
            }
#pragma unroll
            for (int nt = 0; nt < 8; nt++) {
                const int n = warp_n * 64 + nt * 8 + g;
                const uint32_t b0 = B_[n * SSTR + w0];
                const uint32_t b1 = B_[n * SSTR + w0 + 4];
                mma_bf16(acc[0][nt][0], acc[0][nt][1], acc[0][nt][2], acc[0][nt][3],
                         afr[0][0], afr[0][1], afr[0][2], afr[0][3], b0, b1);
                mma_bf16(acc[1][nt][0], acc[1][nt][1], acc[1][nt][2], acc[1][nt][3],
                         afr[1][0], afr[1][1], afr[1][2], afr[1][3], b0, b1);
            }
        }

        if (more) {
            uint32_t* Aw = sA[p ^ 1];
            uint32_t* Bw = sB[p ^ 1];
            *(uint4*)&Aw[cr0 * SSTR + cs0 * 4] = pa0;
            *(uint4*)&Aw[cr1 * SSTR + cs0 * 4] = pa1;
            *(uint4*)&Bw[cr0 * SSTR + cs0 * 4] = pb0;
            *(uint4*)&Bw[cr1 * SSTR + cs0 * 4] = pb1;
        }
        __syncthreads();
        p ^= 1;
    }

    // ---------------- epilogue ----------------
#pragma unroll
    for (int mt = 0; mt < 2; mt++) {
        const int r0 = rowBase + warp_m * 32 + mt * 16 + g;
#pragma unroll
        for (int nt = 0; nt < 8; nt++) {
            const int c = colBase + warp_n * 64 + nt * 8 + 2 * t;
            const float bs0 = bias[c], bs1 = bias[c + 1];
            float x0 = acc[mt][nt][0] + bs0;
            float x1 = acc[mt][nt][1] + bs1;
            float x2 = acc[mt][nt][2] + bs0;
            float x3 = acc[mt][nt][3] + bs1;
            if (relu) {
                x0 = fmaxf(x0, 0.0f); x1 = fmaxf(x1, 0.0f);
                x2 = fmaxf(x2, 0.0f); x3 = fmaxf(x3, 0.0f);
            }
            if (mode == 0) {
                float2 v0 = { x0, x1 };
                float2 v1 = { x2, x3 };
                *(float2*)(Cf + (size_t)r0 * N + c) = v0;
                *(float2*)(Cf + (size_t)(r0 + 8) * N + c) = v1;
            } else {
                __nv_bfloat16 h0, l0, h1, l1, h2, l2, h3, l3;
                bf16_split(x0, h0, l0); bf16_split(x1, h1, l1);
                bf16_split(x2, h2, l2); bf16_split(x3, h3, l3);
                const unsigned hu0 = bf16x2_u32(h0, h1), lu0 = bf16x2_u32(l0, l1);
                const unsigned hu1 = bf16x2_u32(h2, h3), lu1 = bf16x2_u32(l2, l3);
                size_t b0 = (size_t)r0 * (3 * N) + c;
                size_t b1 = (size_t)(r0 + 8) * (3 * N) + c;
                *(unsigned*)(Csp + b0)         = hu0;
                *(unsigned*)(Csp + b0 + N)     = hu0;
                *(unsigned*)(Csp + b0 + 2 * N) = lu0;
                *(unsigned*)(Csp + b1)         = hu1;
                *(unsigned*)(Csp + b1 + N)     = hu1;
                *(unsigned*)(Csp + b1 + 2 * N) = lu1;
            }
        }
    }
}

// ---------------- prep: src_features -> A'_sem [8192][1536] ---------------------
__global__ void prep_a_sem_kernel(const float* __restrict__ feat)
{
    const int m = blockIdx.x;
    __nv_bfloat16* row = g_a_sem + (size_t)m * K3_SEM;
    const float* fr = feat + (size_t)m * CF;
    for (int k = threadIdx.x; k < CF; k += 128) {
        __nv_bfloat16 h, l;
        bf16_split(fr[k], h, l);
        row[k] = h;
        row[CF + k] = h;
        row[2 * CF + k] = l;
    }
}

// ---------------- prep: W [K][N] -> B' [N][K3pad] (h | l | h, zero pad) ---------
__global__ void prep_b_kernel(const float* __restrict__ W,
                              __nv_bfloat16* __restrict__ out,
                              int K, int Kpad, int N, int K3pad)
{
    const int n = blockIdx.x;
    __nv_bfloat16* row = out + (size_t)n * K3pad;
    for (int j = threadIdx.x; j < K3pad; j += 128) {
        __nv_bfloat16 r = __float2bfloat16(0.0f);
        if (j < 3 * Kpad) {
            int third = j / Kpad;
            int k = j - third * Kpad;
            if (k < K) {
                __nv_bfloat16 h, l;
                bf16_split(W[(size_t)k * N + n], h, l);
                r = (third == 1) ? l : h;
            }
        }
        row[j] = r;
    }
}

// ---------------- small SIMT GEMM (N=20 logits) --------------------------------
#define BM 64
#define BN 64
#define BK 16
__global__ void gemm_bias_act_kernel(const float* __restrict__ A,
                                     const float* __restrict__ B,
                                     const float* __restrict__ bias,
                                     float* __restrict__ C,
                                     int M, int N, int K, int relu)
{
    __shared__ float As[BK][BM + 1];
    __shared__ float Bs[BK][BN];
    const int tx = threadIdx.x, ty = threadIdx.y;
    const int tid = ty * 16 + tx;
    const int rowBase = blockIdx.y * BM, colBase = blockIdx.x * BN;
    float acc[4][4];
#pragma unroll
    for (int i = 0; i < 4; i++)
#pragma unroll
        for (int j = 0; j < 4; j++) acc[i][j] = 0.0f;
    const int ar = tid / 16, ac = tid % 16, bn = tid % 64, bk = tid / 64;
    for (int kt = 0; kt < K; kt += BK) {
#pragma unroll
        for (int j = 0; j < 4; j++) {
            int r = ar + j * 16, gr = rowBase + r, gc = kt + ac;
            As[ac][r] = (gc < K) ? A[(size_t)gr * K + gc] : 0.0f;
        }
#pragma unroll
        for (int j = 0; j < 4; j++) {
            int k = bk + j * 4, gk = kt + k, gn = colBase + bn;
            Bs[k][bn] = (gk < K && gn < N) ? B[(size_t)gk * N + gn] : 0.0f;
        }
        __syncthreads();
#pragma unroll
        for (int kk = 0; kk < BK; kk++) {
            float a[4], b[4];
#pragma unroll
            for (int i = 0; i < 4; i++) a[i] = As[kk][ty * 4 + i];
#pragma unroll
            for (int j = 0; j < 4; j++) b[j] = Bs[kk][tx * 4 + j];
#pragma unroll
            for (int i = 0; i < 4; i++)
#pragma unroll
                for (int j = 0; j < 4; j++)
                    acc[i][j] = fmaf(a[i], b[j], acc[i][j]);
        }
        __syncthreads();
    }
#pragma unroll
    for (int i = 0; i < 4; i++) {
        int gr = rowBase + ty * 4 + i;
#pragma unroll
        for (int j = 0; j < 4; j++) {
            int gc = colBase + tx * 4 + j;
            if (gc < N) {
                float v = acc[i][j] + bias[gc];
                if (relu) v = fmaxf(v, 0.0f);
                C[(size_t)gr * N + gc] = v;
            }
        }
    }
}

// ---------------- warp-cooperative 3-NN ----------------------------------------
#define KNN_WARPS 8
#define KNN_TPW   4
#define KNN_TGTPB (KNN_WARPS * KNN_TPW)

__device__ __forceinline__ ull knn_packkey(float r, int j) {
    unsigned u = __float_as_uint(r);
    u = (u & 0x80000000u) ? ~u : (u | 0x80000000u);
    return ((ull)u << 32) | (unsigned)j;
}
__device__ __forceinline__ float knn_unpackr(ull k) {
    unsigned u = (unsigned)(k >> 32);
    u = (u & 0x80000000u) ? (u & 0x7fffffffu) : ~u;
    return __uint_as_float(u);
}
__device__ __forceinline__ void knn_insert(ull& k0, ull& k1, ull& k2, ull k) {
    if (k < k2) {
        if (k < k1) {
            k2 = k1;
            if (k < k0) { k1 = k0; k0 = k; }
            else        { k1 = k; }
        } else k2 = k;
    }
}

__global__ __launch_bounds__(256)
void knn_kernel(const float* __restrict__ src, const float* __restrict__ tgt)
{
    __shared__ float sx[MSRC], sy[MSRC], sz[MSRC];
    const int b = blockIdx.y;
    const float* s = src + (size_t)b * MSRC * 3;
    for (int i = threadIdx.x; i < MSRC; i += 256) {
        sx[i] = s[3 * i + 0]; sy[i] = s[3 * i + 1]; sz[i] = s[3 * i + 2];
    }
    __syncthreads();

    const int warp = threadIdx.x >> 5, lane = threadIdx.x & 31;
    const int tbase = blockIdx.x * KNN_TGTPB + warp * KNN_TPW;

    float px[KNN_TPW], py[KNN_TPW], pz[KNN_TPW], pn[KNN_TPW];
#pragma unroll
    for (int t = 0; t < KNN_TPW; t++) {
        const float* tp = tgt + ((size_t)b * NTGT + tbase + t) * 3;
        px[t] = tp[0]; py[t] = tp[1]; pz[t] = tp[2];
        pn[t] = fmaf(px[t], px[t], fmaf(py[t], py[t], pz[t] * pz[t]));
    }
    float r0[KNN_TPW], r1[KNN_TPW], r2[KNN_TPW];
    int   j0[KNN_TPW], j1[KNN_TPW], j2[KNN_TPW];
#pragma unroll
    for (int t = 0; t < KNN_TPW; t++) {
        r0[t] = r1[t] = r2[t] = 1e30f; j0[t] = j1[t] = j2[t] = 0;
    }
    for (int j = lane; j < MSRC; j += 32) {
        const float x = sx[j], y = sy[j], z = sz[j];
        const float s2 = fmaf(x, x, fmaf(y, y, z * z));
        const float xm2 = -2.0f * x, ym2 = -2.0f * y, zm2 = -2.0f * z;
#pragma unroll
        for (int t = 0; t < KNN_TPW; t++) {
            const float r = fmaf(xm2, px[t], fmaf(ym2, py[t], fmaf(zm2, pz[t], s2)));
            if (r < r2[t]) {
                if (r < r1[t]) {
                    r2[t] = r1[t]; j2[t] = j1[t];
                    if (r < r0[t]) { r1[t] = r0[t]; j1[t] = j0[t]; r0[t] = r; j0[t] = j; }
                    else           { r1[t] = r; j1[t] = j; }
                } else { r2[t] = r; j2[t] = j; }
            }
        }
    }
#pragma unroll
    for (int t = 0; t < KNN_TPW; t++) {
        ull k0 = knn_packkey(r0[t], j0[t]);
        ull k1 = knn_packkey(r1[t], j1[t]);
        ull k2 = knn_packkey(r2[t], j2[t]);
#pragma unroll
        for (int off = 16; off; off >>= 1) {
            ull o0 = __shfl_xor_sync(0xffffffffu, k0, off);
            ull o1 = __shfl_xor_sync(0xffffffffu, k1, off);
            ull o2 = __shfl_xor_sync(0xffffffffu, k2, off);
            knn_insert(k0, k1, k2, o0);
            knn_insert(k0, k1, k2, o1);
            knn_insert(k0, k1, k2, o2);
        }
        if (lane == 0) {
            const size_t base = ((size_t)b * NTGT + tbase + t) * KNN;
            g_knn_idx[base + 0] = (int)(unsigned)k0;
            g_knn_idx[base + 1] = (int)(unsigned)k1;
            g_knn_idx[base + 2] = (int)(unsigned)k2;
            g_knn_d[base + 0] = sqrtf(fmaxf(knn_unpackr(k0) + pn[t], 0.0f));
            g_knn_d[base + 1] = sqrtf(fmaxf(knn_unpackr(k1) + pn[t], 0.0f));
            g_knn_d[base + 2] = sqrtf(fmaxf(knn_unpackr(k2) + pn[t], 0.0f));
        }
    }
}

// ---------------- gather + fuse -> A'_up1 split bf16 [16384][1664] --------------
__global__ void fuse_kernel(const float* __restrict__ feat,
                            const float* __restrict__ sem)
{
    const int row = blockIdx.x;
    const int b = row / NTGT;
    const size_t base = (size_t)row * KNN;

    const int i0 = g_knn_idx[base + 0];
    const int i1 = g_knn_idx[base + 1];
    const int i2 = g_knn_idx[base + 2];
    const float dd0 = g_knn_d[base + 0];
    const float dd1 = g_knn_d[base + 1];
    const float dd2 = g_knn_d[base + 2];

    const float mn = fminf(dd0, fminf(dd1, dd2));
    const float e0 = expf(mn - dd0);
    const float e1 = expf(mn - dd1);
    const float e2 = expf(mn - dd2);
    const float inv = 1.0f / (e0 + e1 + e2);
    const float w0 = e0 * inv, w1 = e1 * inv, w2 = e2 * inv;

    char* crow = (char*)(g_a_up1 + (size_t)row * K3_UP1);   // thirds at cols 0,544,1088
    const int t = threadIdx.x;              // 0..127

    {   // feature part: slot t covers cols 4t..4t+3
        const float4* f0 = (const float4*)(feat + ((size_t)(b * MSRC + i0)) * CF);
        const float4* f1 = (const float4*)(feat + ((size_t)(b * MSRC + i1)) * CF);
        const float4* f2 = (const float4*)(feat + ((size_t)(b * MSRC + i2)) * CF);
        float4 a0 = f0[t], a1 = f1[t], a2 = f2[t];
        float v[4];
        v[0] = fmaf(w0, a0.x, fmaf(w1, a1.x, w2 * a2.x));
        v[1] = fmaf(w0, a0.y, fmaf(w1, a1.y, w2 * a2.y));
        v[2] = fmaf(w0, a0.z, fmaf(w1, a1.z, w2 * a2.z));
        v[3] = fmaf(w0, a0.w, fmaf(w1, a1.w, w2 * a2.w));
        __nv_bfloat16 h[4], l[4];
#pragma unroll
        for (int q = 0; q < 4; q++) bf16_split(v[q], h[q], l[q]);
        ull hu = ((ull)bf16x2_u32(h[2], h[3]) << 32) | bf16x2_u32(h[0], h[1]);
        ull lu = ((ull)bf16x2_u32(l[2], l[3]) << 32) | bf16x2_u32(l[0], l[1]);
        *(ull*)(crow + 8 * t)                 = hu;   // hi third 0 (col 4t)
        *(ull*)(crow + 2 * KP_UP1 + 8 * t)    = hu;   // hi third 1 (col 544+4t)
        *(ull*)(crow + 4 * KP_UP1 + 8 * t)    = lu;   // lo third 2 (col 1088+4t)
    }

    // pad zeros: cols 532..543 in each third + tail 1632..1663
    if (t >= 32 && t < 100) {
        int j = t - 32;
        int col;
        if (j < 12)       col = 532 + j;
        else if (j < 24)  col = 1076 + (j - 12);
        else              col = 1620 + (j - 24);     // covers 1620..1663
        ((__nv_bfloat16*)crow)[col] = __float2bfloat16(0.0f);
    }

    // semantic softmax-mean -> cols 512..531 (warp 0)
    if (t < 32) {
        int idx[3] = { i0, i1, i2 };
        float accsem = 0.0f;
#pragma unroll
        for (int k = 0; k < 3; k++) {
            const float* srow = sem + ((size_t)(b * MSRC + idx[k])) * NCLS;
            float vv = (t < NCLS) ? srow[t] : -1e30f;
            float m = vv;
#pragma unroll
            for (int off = 16; off; off >>= 1)
                m = fmaxf(m, __shfl_xor_sync(0xffffffffu, m, off));
            float e = (t < NCLS) ? expf(vv - m) : 0.0f;
            float ssum = e;
#pragma unroll
            for (int off = 16; off; off >>= 1)
                ssum += __shfl_xor_sync(0xffffffffu, ssum, off);
            accsem += e / ssum;
        }
        if (t < NCLS) {
            float v = accsem * (1.0f / 3.0f);
            __nv_bfloat16 h, l;
            bf16_split(v, h, l);
            __nv_bfloat16* rw = (__nv_bfloat16*)crow;
            rw[512 + t] = h;
            rw[KP_UP1 + 512 + t] = h;
            rw[2 * KP_UP1 + 512 + t] = l;
        }
    }
}

// ---------------- launch --------------------------------------------------------
extern "C" void kernel_launch(void* const* d_in, const int* in_sizes, int n_in,
                              void* d_out, int out_size)
{
    const float* src_points   = (const float*)d_in[0];
    const float* tgt_points   = (const float*)d_in[1];
    const float* src_features = (const float*)d_in[2];
    const float* w_sem1 = (const float*)d_in[3];
    const float* b_sem1 = (const float*)d_in[4];
    const float* w_sem2 = (const float*)d_in[5];
    const float* b_sem2 = (const float*)d_in[6];
    const float* w_up1  = (const float*)d_in[7];
    const float* b_up1  = (const float*)d_in[8];
    const float* w_up2  = (const float*)d_in[9];
    const float* b_up2  = (const float*)d_in[10];

    float* out = (float*)d_out;
    float* sem_out = out + (size_t)BATCH * NTGT * OUTC;

    void* p;
    cudaGetSymbolAddress(&p, g_sem_hidden); float* sem_hidden = (float*)p;
    cudaGetSymbolAddress(&p, g_a_sem);      __nv_bfloat16* a_sem  = (__nv_bfloat16*)p;
    cudaGetSymbolAddress(&p, g_b_sem1);     __nv_bfloat16* bp_sem = (__nv_bfloat16*)p;
    cudaGetSymbolAddress(&p, g_a_up1);      __nv_bfloat16* a_up1  = (__nv_bfloat16*)p;
    cudaGetSymbolAddress(&p, g_b_up1);      __nv_bfloat16* bp_up1 = (__nv_bfloat16*)p;
    cudaGetSymbolAddress(&p, g_a_up2);      __nv_bfloat16* a_up2  = (__nv_bfloat16*)p;
    cudaGetSymbolAddress(&p, g_b_up2);      __nv_bfloat16* bp_up2 = (__nv_bfloat16*)p;

    // weight preps (tiny)
    prep_b_kernel<<<H1, 128>>>(w_sem1, bp_sem, CF, CF, H1, K3_SEM);
    prep_b_kernel<<<H2, 128>>>(w_up1, bp_up1, CIN, KP_UP1, H2, K3_UP1);
    prep_b_kernel<<<OUTC, 128>>>(w_up2, bp_up2, H2, H2, OUTC, K3_UP2);
    // A' for semantic MLP
    prep_a_sem_kernel<<<BATCH * MSRC, 128>>>(src_features);

    // 1) sem hidden = relu(feat @ w_sem1 + b1)  -> fp32 [8192][128]
    gemm_mma_kernel<<<dim3(BATCH * MSRC / 128, H1 / 128), 256>>>(
        a_sem, bp_sem, b_sem1, sem_hidden, nullptr, H1, K3_SEM, 1, 0);

    // 2) logits = hidden @ w_sem2 + b2 -> d_out tail [8192][20]
    gemm_bias_act_kernel<<<dim3(1, BATCH * MSRC / BM), dim3(16, 16)>>>(
        sem_hidden, w_sem2, b_sem2, sem_out, BATCH * MSRC, NCLS, H1, 0);

    // 3) 3-NN
    knn_kernel<<<dim3(NTGT / KNN_TGTPB, BATCH), 256>>>(src_points, tgt_points);

    // 4) fuse -> A'_up1 split bf16
    fuse_kernel<<<BATCH * NTGT, 128>>>(src_features, sem_out);

    // 5) up hidden = relu(combined @ w_up1 + b)  -> A'_up2 split bf16
    gemm_mma_kernel<<<dim3(BATCH * NTGT / 128, H2 / 128), 256>>>(
        a_up1, bp_up1, b_up1, nullptr, a_up2, H2, K3_UP1, 1, 1);

    // 6) out = up_hidden @ w_up2 + b  -> fp32 [16384][512]
    gemm_mma_kernel<<<dim3(BATCH * NTGT / 128, OUTC / 128), 256>>>(
        a_up2, bp_up2, b_up2, out, nullptr, OUTC, K3_UP2, 0, 0);
}

// round 10
// speedup vs baseline: 1.7586x; 1.0369x over previous
#include <cuda_runtime.h>
#include <cuda_bf16.h>
#include <math.h>
#include <cstdint>

#define BATCH 2
#define MSRC  4096
#define NTGT  8192
#define CF    512
#define NCLS  20
#define OUTC  512
#define H1    128
#define H2    256
#define CIN   532
#define KNN   3

// split-K3 sizes (A' = [hi|hi|lo], B' = [hi|lo|hi], zero-padded)
#define K3_SEM  1536          // 3*512
#define KP_UP1  544           // 532 padded to 544
#define K3_UP1  1664          // 3*544=1632 -> pad to 1664
#define K3_UP2  768           // 3*256

typedef unsigned long long ull;

// ---------------- scratch (static device globals; no allocation) ----------------
__device__ __align__(256) float         g_sem_hidden[BATCH * MSRC * H1];
__device__ __align__(256) int           g_knn_idx[BATCH * NTGT * KNN];
__device__ __align__(256) float         g_knn_d[BATCH * NTGT * KNN];
__device__ __align__(256) ull           g_knn_cand[BATCH * NTGT * 2 * KNN];
__device__ __align__(256) __nv_bfloat16 g_a_sem[(size_t)BATCH * MSRC * K3_SEM];
__device__ __align__(256) __nv_bfloat16 g_b_sem1[H1 * K3_SEM];
__device__ __align__(256) __nv_bfloat16 g_a_up1[(size_t)BATCH * NTGT * K3_UP1];
__device__ __align__(256) __nv_bfloat16 g_b_up1[H2 * K3_UP1];
__device__ __align__(256) __nv_bfloat16 g_a_up2[(size_t)BATCH * NTGT * K3_UP2];
__device__ __align__(256) __nv_bfloat16 g_b_up2[OUTC * K3_UP2];

// ---------------- helpers -------------------------------------------------------
__device__ __forceinline__ void bf16_split(float v, __nv_bfloat16& h, __nv_bfloat16& l) {
    h = __float2bfloat16(v);
    l = __float2bfloat16(v - __bfloat162float(h));
}
__device__ __forceinline__ unsigned bf16x2_u32(__nv_bfloat16 a, __nv_bfloat16 b) {
    __nv_bfloat162 t; t.x = a; t.y = b;
    return *(unsigned*)&t;
}
__device__ __forceinline__ void mma_bf16(float& d0, float& d1, float& d2, float& d3,
                                         uint32_t a0, uint32_t a1, uint32_t a2, uint32_t a3,
                                         uint32_t b0, uint32_t b1) {
    asm volatile(
        "mma.sync.aligned.m16n8k16.row.col.f32.bf16.bf16.f32 "
        "{%0,%1,%2,%3}, {%4,%5,%6,%7}, {%8,%9}, {%0,%1,%2,%3};"
        : "+f"(d0), "+f"(d1), "+f"(d2), "+f"(d3)
        : "r"(a0), "r"(a1), "r"(a2), "r"(a3), "r"(b0), "r"(b1));
}

// ================= mma.sync split-bf16 GEMM (unchanged from R9) =================
#define SSTR 20                   // words per row (32 bf16 = 16 words + 4 pad)

__global__ __launch_bounds__(256)
void gemm_mma_kernel(const __nv_bfloat16* __restrict__ Ap,
                     const __nv_bfloat16* __restrict__ Bp,
                     const float* __restrict__ bias,
                     float* __restrict__ Cf,
                     __nv_bfloat16* __restrict__ Csp,
                     int N, int K3, int relu, int mode)
{
    __shared__ uint32_t sA[2][128 * SSTR];
    __shared__ uint32_t sB[2][128 * SSTR];

    const int tid = threadIdx.x;
    const int wid = tid >> 5;
    const int lane = tid & 31;
    const int g = lane >> 2;
    const int t = lane & 3;

    const int warp_m = wid & 3;
    const int warp_n = wid >> 2;

    const int rowBase = blockIdx.x * 128;
    const int colBase = blockIdx.y * 128;

    const int cr0 = tid >> 2, cs0 = tid & 3;
    const int cr1 = (tid + 256) >> 2;
    const size_t krow = (size_t)K3 * 2;

    const char* Agp = (const char*)Ap + (size_t)(rowBase + cr0) * krow + cs0 * 16;
    const char* Agp1 = (const char*)Ap + (size_t)(rowBase + cr1) * krow + cs0 * 16;
    const char* Bgp = (const char*)Bp + (size_t)(colBase + cr0) * krow + cs0 * 16;
    const char* Bgp1 = (const char*)Bp + (size_t)(colBase + cr1) * krow + cs0 * 16;

    float acc[2][8][4];
#pragma unroll
    for (int i = 0; i < 2; i++)
#pragma unroll
        for (int j = 0; j < 8; j++)
#pragma unroll
            for (int q = 0; q < 4; q++) acc[i][j][q] = 0.0f;

    const int chunks = K3 >> 5;

    {
        uint4 a0 = *(const uint4*)(Agp);
        uint4 a1 = *(const uint4*)(Agp1);
        uint4 b0 = *(const uint4*)(Bgp);
        uint4 b1 = *(const uint4*)(Bgp1);
        *(uint4*)&sA[0][cr0 * SSTR + cs0 * 4] = a0;
        *(uint4*)&sA[0][cr1 * SSTR + cs0 * 4] = a1;
        *(uint4*)&sB[0][cr0 * SSTR + cs0 * 4] = b0;
        *(uint4*)&sB[0][cr1 * SSTR + cs0 * 4] = b1;
    }
    __syncthreads();

    int p = 0;
    for (int ch = 0; ch < chunks; ch++) {
        uint4 pa0, pa1, pb0, pb1;
        const bool more = (ch + 1 < chunks);
        if (more) {
            const size_t off = (size_t)(ch + 1) * 64;
            pa0 = *(const uint4*)(Agp + off);
            pa1 = *(const uint4*)(Agp1 + off);
            pb0 = *(const uint4*)(Bgp + off);
            pb1 = *(const uint4*)(Bgp1 + off);
        }

        const uint32_t* A_ = sA[p];
        const uint32_t* B_ = sB[p];
#pragma unroll
        for (int s = 0; s < 2; s++) {
            const int w0 = s * 8 + t;
            uint32_t afr[2][4];
#pragma unroll
            for (int mt = 0; mt < 2; mt++) {
                const int r = warp_m * 32 + mt * 16 + g;
                afr[mt][0] = A_[r * SSTR + w0];
                afr[mt][1] = A_[(r + 8) * SSTR + w0];
                afr[mt][2] = A_[r * SSTR + w0 + 4];
                afr[mt][3] = A_[(r + 8) * SSTR + w0 + 4];
            }
#pragma unroll
            for (int nt = 0; nt < 8; nt++) {
                const int n = warp_n * 64 + nt * 8 + g;
                const uint32_t b0 = B_[n * SSTR + w0];
                const uint32_t b1 = B_[n * SSTR + w0 + 4];
                mma_bf16(acc[0][nt][0], acc[0][nt][1], acc[0][nt][2], acc[0][nt][3],
                         afr[0][0], afr[0][1], afr[0][2], afr[0][3], b0, b1);
                mma_bf16(acc[1][nt][0], acc[1][nt][1], acc[1][nt][2], acc[1][nt][3],
                         afr[1][0], afr[1][1], afr[1][2], afr[1][3], b0, b1);
            }
        }

        if (more) {
            uint32_t* Aw = sA[p ^ 1];
            uint32_t* Bw = sB[p ^ 1];
            *(uint4*)&Aw[cr0 * SSTR + cs0 * 4] = pa0;
            *(uint4*)&Aw[cr1 * SSTR + cs0 * 4] = pa1;
            *(uint4*)&Bw[cr0 * SSTR + cs0 * 4] = pb0;
            *(uint4*)&Bw[cr1 * SSTR + cs0 * 4] = pb1;
        }
        __syncthreads();
        p ^= 1;
    }

#pragma unroll
    for (int mt = 0; mt < 2; mt++) {
        const int r0 = rowBase + warp_m * 32 + mt * 16 + g;
#pragma unroll
        for (int nt = 0; nt < 8; nt++) {
            const int c = colBase + warp_n * 64 + nt * 8 + 2 * t;
            const float bs0 = bias[c], bs1 = bias[c + 1];
            float x0 = acc[mt][nt][0] + bs0;
            float x1 = acc[mt][nt][1] + bs1;
            float x2 = acc[mt][nt][2] + bs0;
            float x3 = acc[mt][nt][3] + bs1;
            if (relu) {
                x0 = fmaxf(x0, 0.0f); x1 = fmaxf(x1, 0.0f);
                x2 = fmaxf(x2, 0.0f); x3 = fmaxf(x3, 0.0f);
            }
            if (mode == 0) {
                float2 v0 = { x0, x1 };
                float2 v1 = { x2, x3 };
                *(float2*)(Cf + (size_t)r0 * N + c) = v0;
                *(float2*)(Cf + (size_t)(r0 + 8) * N + c) = v1;
            } else {
                __nv_bfloat16 h0, l0, h1, l1, h2, l2, h3, l3;
                bf16_split(x0, h0, l0); bf16_split(x1, h1, l1);
                bf16_split(x2, h2, l2); bf16_split(x3, h3, l3);
                const unsigned hu0 = bf16x2_u32(h0, h1), lu0 = bf16x2_u32(l0, l1);
                const unsigned hu1 = bf16x2_u32(h2, h3), lu1 = bf16x2_u32(l2, l3);
                size_t b0 = (size_t)r0 * (3 * N) + c;
                size_t b1 = (size_t)(r0 + 8) * (3 * N) + c;
                *(unsigned*)(Csp + b0)         = hu0;
                *(unsigned*)(Csp + b0 + N)     = hu0;
                *(unsigned*)(Csp + b0 + 2 * N) = lu0;
                *(unsigned*)(Csp + b1)         = hu1;
                *(unsigned*)(Csp + b1 + N)     = hu1;
                *(unsigned*)(Csp + b1 + 2 * N) = lu1;
            }
        }
    }
}

// ---------------- prep: src_features -> A'_sem (vectorized) ---------------------
__global__ void prep_a_sem_kernel(const float* __restrict__ feat)
{
    const int m = blockIdx.x;
    const int t = threadIdx.x;                 // 0..127, cols 4t..4t+3
    char* row = (char*)(g_a_sem + (size_t)m * K3_SEM);
    const float4 v = ((const float4*)(feat + (size_t)m * CF))[t];
    __nv_bfloat16 h[4], l[4];
    bf16_split(v.x, h[0], l[0]);
    bf16_split(v.y, h[1], l[1]);
    bf16_split(v.z, h[2], l[2]);
    bf16_split(v.w, h[3], l[3]);
    ull hu = ((ull)bf16x2_u32(h[2], h[3]) << 32) | bf16x2_u32(h[0], h[1]);
    ull lu = ((ull)bf16x2_u32(l[2], l[3]) << 32) | bf16x2_u32(l[0], l[1]);
    *(ull*)(row + 8 * t)                = hu;
    *(ull*)(row + 2 * CF + 8 * t)       = hu;
    *(ull*)(row + 4 * CF + 8 * t)       = lu;
}

// ---------------- prep: W [K][N] -> B' [N][K3pad] (h | l | h, zero pad) ---------
__global__ void prep_b_kernel(const float* __restrict__ W,
                              __nv_bfloat16* __restrict__ out,
                              int K, int Kpad, int N, int K3pad)
{
    const int n = blockIdx.x;
    __nv_bfloat16* row = out + (size_t)n * K3pad;
    for (int j = threadIdx.x; j < K3pad; j += 128) {
        __nv_bfloat16 r = __float2bfloat16(0.0f);
        if (j < 3 * Kpad) {
            int third = j / Kpad;
            int k = j - third * Kpad;
            if (k < K) {
                __nv_bfloat16 h, l;
                bf16_split(W[(size_t)k * N + n], h, l);
                r = (third == 1) ? l : h;
            }
        }
        row[j] = r;
    }
}

// ---------------- small SIMT GEMM (N=20 logits) --------------------------------
#define BM 64
#define BN 64
#define BK 16
__global__ void gemm_bias_act_kernel(const float* __restrict__ A,
                                     const float* __restrict__ B,
                                     const float* __restrict__ bias,
                                     float* __restrict__ C,
                                     int M, int N, int K, int relu)
{
    __shared__ float As[BK][BM + 1];
    __shared__ float Bs[BK][BN];
    const int tx = threadIdx.x, ty = threadIdx.y;
    const int tid = ty * 16 + tx;
    const int rowBase = blockIdx.y * BM, colBase = blockIdx.x * BN;
    float acc[4][4];
#pragma unroll
    for (int i = 0; i < 4; i++)
#pragma unroll
        for (int j = 0; j < 4; j++) acc[i][j] = 0.0f;
    const int ar = tid / 16, ac = tid % 16, bn = tid % 64, bk = tid / 64;
    for (int kt = 0; kt < K; kt += BK) {
#pragma unroll
        for (int j = 0; j < 4; j++) {
            int r = ar + j * 16, gr = rowBase + r, gc = kt + ac;
            As[ac][r] = (gc < K) ? A[(size_t)gr * K + gc] : 0.0f;
        }
#pragma unroll
        for (int j = 0; j < 4; j++) {
            int k = bk + j * 4, gk = kt + k, gn = colBase + bn;
            Bs[k][bn] = (gk < K && gn < N) ? B[(size_t)gk * N + gn] : 0.0f;
        }
        __syncthreads();
#pragma unroll
        for (int kk = 0; kk < BK; kk++) {
            float a[4], b[4];
#pragma unroll
            for (int i = 0; i < 4; i++) a[i] = As[kk][ty * 4 + i];
#pragma unroll
            for (int j = 0; j < 4; j++) b[j] = Bs[kk][tx * 4 + j];
#pragma unroll
            for (int i = 0; i < 4; i++)
#pragma unroll
                for (int j = 0; j < 4; j++)
                    acc[i][j] = fmaf(a[i], b[j], acc[i][j]);
        }
        __syncthreads();
    }
#pragma unroll
    for (int i = 0; i < 4; i++) {
        int gr = rowBase + ty * 4 + i;
#pragma unroll
        for (int j = 0; j < 4; j++) {
            int gc = colBase + tx * 4 + j;
            if (gc < N) {
                float v = acc[i][j] + bias[gc];
                if (relu) v = fmaxf(v, 0.0f);
                C[(size_t)gr * N + gc] = v;
            }
        }
    }
}

// ---------------- KNN: two-phase split-source ----------------------------------
#define KH        2048                   // sources per block (half of MSRC)
#define KNN_TPW   4
#define KNN_TGTPB 32                     // 8 warps * 4 targets

__device__ __forceinline__ ull knn_packkey(float r, int j) {
    unsigned u = __float_as_uint(r);
    u = (u & 0x80000000u) ? ~u : (u | 0x80000000u);
    return ((ull)u << 32) | (unsigned)j;
}
__device__ __forceinline__ float knn_unpackr(ull k) {
    unsigned u = (unsigned)(k >> 32);
    u = (u & 0x80000000u) ? (u & 0x7fffffffu) : ~u;
    return __uint_as_float(u);
}
__device__ __forceinline__ void knn_insert(ull& k0, ull& k1, ull& k2, ull k) {
    if (k < k2) {
        if (k < k1) {
            k2 = k1;
            if (k < k0) { k1 = k0; k0 = k; }
            else        { k1 = k; }
        } else k2 = k;
    }
}
__device__ __forceinline__ void knn_insert_f(float& d0, float& d1, float& d2,
                                             int& i0, int& i1, int& i2,
                                             float r, int j) {
    if (r < d2) {
        if (r < d1) {
            d2 = d1; i2 = i1;
            if (r < d0) { d1 = d0; i1 = i0; d0 = r; i0 = j; }
            else        { d1 = r; i1 = j; }
        } else { d2 = r; i2 = j; }
    }
}

// phase 1: grid (NTGT/32, 2 halves, BATCH); block 256
__global__ __launch_bounds__(256)
void knn_part_kernel(const float* __restrict__ src, const float* __restrict__ tgt)
{
    __shared__ float sx[KH], sy[KH], sz[KH];   // 24 KB
    const int b = blockIdx.z;
    const int h = blockIdx.y;
    const int jbase = h * KH;
    const float* s = src + ((size_t)b * MSRC + jbase) * 3;
    for (int i = threadIdx.x; i < KH; i += 256) {
        sx[i] = s[3 * i + 0]; sy[i] = s[3 * i + 1]; sz[i] = s[3 * i + 2];
    }
    __syncthreads();

    const int warp = threadIdx.x >> 5, lane = threadIdx.x & 31;
    const int tbase = blockIdx.x * KNN_TGTPB + warp * KNN_TPW;

    float qx[KNN_TPW], qy[KNN_TPW], qz[KNN_TPW];
#pragma unroll
    for (int t = 0; t < KNN_TPW; t++) {
        const float* tp = tgt + ((size_t)b * NTGT + tbase + t) * 3;
        qx[t] = -2.0f * tp[0]; qy[t] = -2.0f * tp[1]; qz[t] = -2.0f * tp[2];
    }

    float d0[KNN_TPW], d1[KNN_TPW], d2[KNN_TPW];
    int   i0[KNN_TPW], i1[KNN_TPW], i2[KNN_TPW];
#pragma unroll
    for (int t = 0; t < KNN_TPW; t++) {
        d0[t] = d1[t] = d2[t] = 1e30f; i0[t] = i1[t] = i2[t] = 0;
    }

    for (int j = lane; j < KH; j += 64) {
        const int ja = j, jb = j + 32;
        const float xa = sx[ja], ya = sy[ja], za = sz[ja];
        const float xb = sx[jb], yb = sy[jb], zb = sz[jb];
        const float s2a = fmaf(xa, xa, fmaf(ya, ya, za * za));
        const float s2b = fmaf(xb, xb, fmaf(yb, yb, zb * zb));
        float ra[KNN_TPW], rb[KNN_TPW];
#pragma unroll
        for (int t = 0; t < KNN_TPW; t++)
            ra[t] = fmaf(xa, qx[t], fmaf(ya, qy[t], fmaf(za, qz[t], s2a)));
#pragma unroll
        for (int t = 0; t < KNN_TPW; t++)
            rb[t] = fmaf(xb, qx[t], fmaf(yb, qy[t], fmaf(zb, qz[t], s2b)));
#pragma unroll
        for (int t = 0; t < KNN_TPW; t++) {
            knn_insert_f(d0[t], d1[t], d2[t], i0[t], i1[t], i2[t], ra[t], ja);
            knn_insert_f(d0[t], d1[t], d2[t], i0[t], i1[t], i2[t], rb[t], jb);
        }
    }

#pragma unroll
    for (int t = 0; t < KNN_TPW; t++) {
        ull k0 = knn_packkey(d0[t], jbase + i0[t]);
        ull k1 = knn_packkey(d1[t], jbase + i1[t]);
        ull k2 = knn_packkey(d2[t], jbase + i2[t]);
#pragma unroll
        for (int off = 16; off; off >>= 1) {
            ull o0 = __shfl_xor_sync(0xffffffffu, k0, off);
            ull o1 = __shfl_xor_sync(0xffffffffu, k1, off);
            ull o2 = __shfl_xor_sync(0xffffffffu, k2, off);
            knn_insert(k0, k1, k2, o0);
            knn_insert(k0, k1, k2, o1);
            knn_insert(k0, k1, k2, o2);
        }
        if (lane == 0) {
            const size_t base = (((size_t)b * NTGT + tbase + t) * 2 + h) * KNN;
            g_knn_cand[base + 0] = k0;
            g_knn_cand[base + 1] = k1;
            g_knn_cand[base + 2] = k2;
        }
    }
}

// phase 2: merge 6 candidates -> top3, compute distances
__global__ void knn_merge_kernel(const float* __restrict__ tgt)
{
    const int row = blockIdx.x * 256 + threadIdx.x;
    if (row >= BATCH * NTGT) return;
    const ull* cand = g_knn_cand + (size_t)row * 2 * KNN;
    ull k0 = cand[0], k1 = cand[1], k2 = cand[2];
    knn_insert(k0, k1, k2, cand[3]);
    knn_insert(k0, k1, k2, cand[4]);
    knn_insert(k0, k1, k2, cand[5]);

    const float* tp = tgt + (size_t)row * 3;
    const float pn = fmaf(tp[0], tp[0], fmaf(tp[1], tp[1], tp[2] * tp[2]));

    const size_t base = (size_t)row * KNN;
    g_knn_idx[base + 0] = (int)(unsigned)k0;
    g_knn_idx[base + 1] = (int)(unsigned)k1;
    g_knn_idx[base + 2] = (int)(unsigned)k2;
    g_knn_d[base + 0] = sqrtf(fmaxf(knn_unpackr(k0) + pn, 0.0f));
    g_knn_d[base + 1] = sqrtf(fmaxf(knn_unpackr(k1) + pn, 0.0f));
    g_knn_d[base + 2] = sqrtf(fmaxf(knn_unpackr(k2) + pn, 0.0f));
}

// ---------------- gather + fuse -> A'_up1 split bf16 [16384][1664] --------------
__global__ void fuse_kernel(const float* __restrict__ feat,
                            const float* __restrict__ sem)
{
    const int row = blockIdx.x;
    const int b = row / NTGT;
    const size_t base = (size_t)row * KNN;

    const int i0 = g_knn_idx[base + 0];
    const int i1 = g_knn_idx[base + 1];
    const int i2 = g_knn_idx[base + 2];
    const float dd0 = g_knn_d[base + 0];
    const float dd1 = g_knn_d[base + 1];
    const float dd2 = g_knn_d[base + 2];

    const float mn = fminf(dd0, fminf(dd1, dd2));
    const float e0 = expf(mn - dd0);
    const float e1 = expf(mn - dd1);
    const float e2 = expf(mn - dd2);
    const float inv = 1.0f / (e0 + e1 + e2);
    const float w0 = e0 * inv, w1 = e1 * inv, w2 = e2 * inv;

    char* crow = (char*)(g_a_up1 + (size_t)row * K3_UP1);
    const int t = threadIdx.x;              // 0..127

    {
        const float4* f0 = (const float4*)(feat + ((size_t)(b * MSRC + i0)) * CF);
        const float4* f1 = (const float4*)(feat + ((size_t)(b * MSRC + i1)) * CF);
        const float4* f2 = (const float4*)(feat + ((size_t)(b * MSRC + i2)) * CF);
        float4 a0 = f0[t], a1 = f1[t], a2 = f2[t];
        float v[4];
        v[0] = fmaf(w0, a0.x, fmaf(w1, a1.x, w2 * a2.x));
        v[1] = fmaf(w0, a0.y, fmaf(w1, a1.y, w2 * a2.y));
        v[2] = fmaf(w0, a0.z, fmaf(w1, a1.z, w2 * a2.z));
        v[3] = fmaf(w0, a0.w, fmaf(w1, a1.w, w2 * a2.w));
        __nv_bfloat16 h[4], l[4];
#pragma unroll
        for (int q = 0; q < 4; q++) bf16_split(v[q], h[q], l[q]);
        ull hu = ((ull)bf16x2_u32(h[2], h[3]) << 32) | bf16x2_u32(h[0], h[1]);
        ull lu = ((ull)bf16x2_u32(l[2], l[3]) << 32) | bf16x2_u32(l[0], l[1]);
        *(ull*)(crow + 8 * t)                 = hu;
        *(ull*)(crow + 2 * KP_UP1 + 8 * t)    = hu;
        *(ull*)(crow + 4 * KP_UP1 + 8 * t)    = lu;
    }

    if (t >= 32 && t < 100) {
        int j = t - 32;
        int col;
        if (j < 12)       col = 532 + j;
        else if (j < 24)  col = 1076 + (j - 12);
        else              col = 1620 + (j - 24);
        ((__nv_bfloat16*)crow)[col] = __float2bfloat16(0.0f);
    }

    if (t < 32) {
        int idx[3] = { i0, i1, i2 };
        float accsem = 0.0f;
#pragma unroll
        for (int k = 0; k < 3; k++) {
            const float* srow = sem + ((size_t)(b * MSRC + idx[k])) * NCLS;
            float vv = (t < NCLS) ? srow[t] : -1e30f;
            float m = vv;
#pragma unroll
            for (int off = 16; off; off >>= 1)
                m = fmaxf(m, __shfl_xor_sync(0xffffffffu, m, off));
            float e = (t < NCLS) ? expf(vv - m) : 0.0f;
            float ssum = e;
#pragma unroll
            for (int off = 16; off; off >>= 1)
                ssum += __shfl_xor_sync(0xffffffffu, ssum, off);
            accsem += e / ssum;
        }
        if (t < NCLS) {
            float v = accsem * (1.0f / 3.0f);
            __nv_bfloat16 h, l;
            bf16_split(v, h, l);
            __nv_bfloat16* rw = (__nv_bfloat16*)crow;
            rw[512 + t] = h;
            rw[KP_UP1 + 512 + t] = h;
            rw[2 * KP_UP1 + 512 + t] = l;
        }
    }
}

// ---------------- launch --------------------------------------------------------
extern "C" void kernel_launch(void* const* d_in, const int* in_sizes, int n_in,
                              void* d_out, int out_size)
{
    const float* src_points   = (const float*)d_in[0];
    const float* tgt_points   = (const float*)d_in[1];
    const float* src_features = (const float*)d_in[2];
    const float* w_sem1 = (const float*)d_in[3];
    const float* b_sem1 = (const float*)d_in[4];
    const float* w_sem2 = (const float*)d_in[5];
    const float* b_sem2 = (const float*)d_in[6];
    const float* w_up1  = (const float*)d_in[7];
    const float* b_up1  = (const float*)d_in[8];
    const float* w_up2  = (const float*)d_in[9];
    const float* b_up2  = (const float*)d_in[10];

    float* out = (float*)d_out;
    float* sem_out = out + (size_t)BATCH * NTGT * OUTC;

    void* p;
    cudaGetSymbolAddress(&p, g_sem_hidden); float* sem_hidden = (float*)p;
    cudaGetSymbolAddress(&p, g_a_sem);      __nv_bfloat16* a_sem  = (__nv_bfloat16*)p;
    cudaGetSymbolAddress(&p, g_b_sem1);     __nv_bfloat16* bp_sem = (__nv_bfloat16*)p;
    cudaGetSymbolAddress(&p, g_a_up1);      __nv_bfloat16* a_up1  = (__nv_bfloat16*)p;
    cudaGetSymbolAddress(&p, g_b_up1);      __nv_bfloat16* bp_up1 = (__nv_bfloat16*)p;
    cudaGetSymbolAddress(&p, g_a_up2);      __nv_bfloat16* a_up2  = (__nv_bfloat16*)p;
    cudaGetSymbolAddress(&p, g_b_up2);      __nv_bfloat16* bp_up2 = (__nv_bfloat16*)p;

    // weight preps (tiny)
    prep_b_kernel<<<H1, 128>>>(w_sem1, bp_sem, CF, CF, H1, K3_SEM);
    prep_b_kernel<<<H2, 128>>>(w_up1, bp_up1, CIN, KP_UP1, H2, K3_UP1);
    prep_b_kernel<<<OUTC, 128>>>(w_up2, bp_up2, H2, H2, OUTC, K3_UP2);
    // A' for semantic MLP (vectorized)
    prep_a_sem_kernel<<<BATCH * MSRC, 128>>>(src_features);

    // 1) sem hidden = relu(feat @ w_sem1 + b1)  -> fp32 [8192][128]
    gemm_mma_kernel<<<dim3(BATCH * MSRC / 128, H1 / 128), 256>>>(
        a_sem, bp_sem, b_sem1, sem_hidden, nullptr, H1, K3_SEM, 1, 0);

    // 2) logits = hidden @ w_sem2 + b2 -> d_out tail [8192][20]
    gemm_bias_act_kernel<<<dim3(1, BATCH * MSRC / BM), dim3(16, 16)>>>(
        sem_hidden, w_sem2, b_sem2, sem_out, BATCH * MSRC, NCLS, H1, 0);

    // 3) 3-NN: two-phase
    knn_part_kernel<<<dim3(NTGT / KNN_TGTPB, 2, BATCH), 256>>>(src_points, tgt_points);
    knn_merge_kernel<<<(BATCH * NTGT + 255) / 256, 256>>>(tgt_points);

    // 4) fuse -> A'_up1 split bf16
    fuse_kernel<<<BATCH * NTGT, 128>>>(src_features, sem_out);

    // 5) up hidden = relu(combined @ w_up1 + b)  -> A'_up2 split bf16
    gemm_mma_kernel<<<dim3(BATCH * NTGT / 128, H2 / 128), 256>>>(
        a_up1, bp_up1, b_up1, nullptr, a_up2, H2, K3_UP1, 1, 1);

    // 6) out = up_hidden @ w_up2 + b  -> fp32 [16384][512]
    gemm_mma_kernel<<<dim3(BATCH * NTGT / 128, OUTC / 128), 256>>>(
        a_up2, bp_up2, b_up2, out, nullptr, OUTC, K3_UP2, 0, 0);
}

// round 11
// speedup vs baseline: 1.7818x; 1.0132x over previous
#include <cuda_runtime.h>
#include <cuda_bf16.h>
#include <math.h>
#include <cstdint>

#define BATCH 2
#define MSRC  4096
#define NTGT  8192
#define CF    512
#define NCLS  20
#define OUTC  512
#define H1    128
#define H2    256
#define CIN   532
#define KNN   3

// Split storage: A2 = [hi | lo] (2*Kpad cols); GEMM remaps logical thirds
// (A: hi,hi,lo / B: hi,lo,hi) onto this storage chunk-by-chunk.
#define KP_SEM  512
#define KP_UP1  544           // 532 padded to 544
#define KP_UP2  256
#define K2_SEM  1024
#define K2_UP1  1088
#define K2_UP2  512
#define CPT_SEM 16            // 32-wide K chunks per third
#define CPT_UP1 17
#define CPT_UP2 8

typedef unsigned long long ull;

// ---------------- scratch (static device globals; no allocation) ----------------
__device__ __align__(256) float         g_sem_hidden[BATCH * MSRC * H1];
__device__ __align__(256) int           g_knn_idx[BATCH * NTGT * KNN];
__device__ __align__(256) float         g_knn_d[BATCH * NTGT * KNN];
__device__ __align__(256) ull           g_knn_cand[BATCH * NTGT * 2 * KNN];
__device__ __align__(256) __nv_bfloat16 g_a_sem[(size_t)BATCH * MSRC * K2_SEM];
__device__ __align__(256) __nv_bfloat16 g_b_sem1[H1 * K2_SEM];
__device__ __align__(256) __nv_bfloat16 g_a_up1[(size_t)BATCH * NTGT * K2_UP1];
__device__ __align__(256) __nv_bfloat16 g_b_up1[H2 * K2_UP1];
__device__ __align__(256) __nv_bfloat16 g_a_up2[(size_t)BATCH * NTGT * K2_UP2];
__device__ __align__(256) __nv_bfloat16 g_b_up2[OUTC * K2_UP2];

// ---------------- helpers -------------------------------------------------------
__device__ __forceinline__ void bf16_split(float v, __nv_bfloat16& h, __nv_bfloat16& l) {
    h = __float2bfloat16(v);
    l = __float2bfloat16(v - __bfloat162float(h));
}
__device__ __forceinline__ unsigned bf16x2_u32(__nv_bfloat16 a, __nv_bfloat16 b) {
    __nv_bfloat162 t; t.x = a; t.y = b;
    return *(unsigned*)&t;
}
__device__ __forceinline__ void mma_bf16(float& d0, float& d1, float& d2, float& d3,
                                         uint32_t a0, uint32_t a1, uint32_t a2, uint32_t a3,
                                         uint32_t b0, uint32_t b1) {
    asm volatile(
        "mma.sync.aligned.m16n8k16.row.col.f32.bf16.bf16.f32 "
        "{%0,%1,%2,%3}, {%4,%5,%6,%7}, {%8,%9}, {%0,%1,%2,%3};"
        : "+f"(d0), "+f"(d1), "+f"(d2), "+f"(d3)
        : "r"(a0), "r"(a1), "r"(a2), "r"(a3), "r"(b0), "r"(b1));
}

// chunk remap: logical chunk ch (of 3*CPT) -> stored chunk in [hi|lo]
__device__ __forceinline__ void remap_chunk(int ch, int CPT, int& a_ch, int& b_ch) {
    int c = ch;
    int t = 0;
    if (ch >= 2 * CPT)      { t = 2; c = ch - 2 * CPT; }
    else if (ch >= CPT)     { t = 1; c = ch - CPT; }
    a_ch = (t == 2) ? CPT + c : c;   // A thirds: hi, hi, lo
    b_ch = (t == 1) ? CPT + c : c;   // B thirds: hi, lo, hi
}

// ================= mma.sync split-bf16 GEMM =====================================
// D[M x N] = sum over 3*CPT logical k32-chunks of A2/B2 (stored [hi|lo]).
// mode 0: write fp32 C.  mode 1: write split bf16 [M][2N] as (h | l).
#define SSTR 20                   // words per row (32 bf16 = 16 words + 4 pad)

__global__ __launch_bounds__(256)
void gemm_mma_kernel(const __nv_bfloat16* __restrict__ Ap,
                     const __nv_bfloat16* __restrict__ Bp,
                     const float* __restrict__ bias,
                     float* __restrict__ Cf,
                     __nv_bfloat16* __restrict__ Csp,
                     int N, int CPT, int Kstore, int relu, int mode)
{
    __shared__ uint32_t sA[2][128 * SSTR];
    __shared__ uint32_t sB[2][128 * SSTR];

    const int tid = threadIdx.x;
    const int wid = tid >> 5;
    const int lane = tid & 31;
    const int g = lane >> 2;
    const int t = lane & 3;

    const int warp_m = wid & 3;
    const int warp_n = wid >> 2;

    const int rowBase = blockIdx.x * 128;
    const int colBase = blockIdx.y * 128;

    const int cr0 = tid >> 2, cs0 = tid & 3;
    const int cr1 = (tid + 256) >> 2;
    const size_t krow = (size_t)Kstore * 2;      // bytes per stored row

    const char* Agp  = (const char*)Ap + (size_t)(rowBase + cr0) * krow + cs0 * 16;
    const char* Agp1 = (const char*)Ap + (size_t)(rowBase + cr1) * krow + cs0 * 16;
    const char* Bgp  = (const char*)Bp + (size_t)(colBase + cr0) * krow + cs0 * 16;
    const char* Bgp1 = (const char*)Bp + (size_t)(colBase + cr1) * krow + cs0 * 16;

    float acc[2][8][4];
#pragma unroll
    for (int i = 0; i < 2; i++)
#pragma unroll
        for (int j = 0; j < 8; j++)
#pragma unroll
            for (int q = 0; q < 4; q++) acc[i][j][q] = 0.0f;

    const int chunks = 3 * CPT;

    // prologue: logical chunk 0 -> stored chunk 0 for both
    {
        uint4 a0 = *(const uint4*)(Agp);
        uint4 a1 = *(const uint4*)(Agp1);
        uint4 b0 = *(const uint4*)(Bgp);
        uint4 b1 = *(const uint4*)(Bgp1);
        *(uint4*)&sA[0][cr0 * SSTR + cs0 * 4] = a0;
        *(uint4*)&sA[0][cr1 * SSTR + cs0 * 4] = a1;
        *(uint4*)&sB[0][cr0 * SSTR + cs0 * 4] = b0;
        *(uint4*)&sB[0][cr1 * SSTR + cs0 * 4] = b1;
    }
    __syncthreads();

    int p = 0;
    for (int ch = 0; ch < chunks; ch++) {
        uint4 pa0, pa1, pb0, pb1;
        const bool more = (ch + 1 < chunks);
        if (more) {
            int a_ch, b_ch;
            remap_chunk(ch + 1, CPT, a_ch, b_ch);
            const size_t aoff = (size_t)a_ch * 64;
            const size_t boff = (size_t)b_ch * 64;
            pa0 = *(const uint4*)(Agp + aoff);
            pa1 = *(const uint4*)(Agp1 + aoff);
            pb0 = *(const uint4*)(Bgp + boff);
            pb1 = *(const uint4*)(Bgp1 + boff);
        }

        const uint32_t* A_ = sA[p];
        const uint32_t* B_ = sB[p];
#pragma unroll
        for (int s = 0; s < 2; s++) {
            const int w0 = s * 8 + t;
            uint32_t afr[2][4];
#pragma unroll
            for (int mt = 0; mt < 2; mt++) {
                const int r = warp_m * 32 + mt * 16 + g;
                afr[mt][0] = A_[r * SSTR + w0];
                afr[mt][1] = A_[(r + 8) * SSTR + w0];
                afr[mt][2] = A_[r * SSTR + w0 + 4];
                afr[mt][3] = A_[(r + 8) * SSTR + w0 + 4];
            }
#pragma unroll
            for (int nt = 0; nt < 8; nt++) {
                const int n = warp_n * 64 + nt * 8 + g;
                const uint32_t b0 = B_[n * SSTR + w0];
                const uint32_t b1 = B_[n * SSTR + w0 + 4];
                mma_bf16(acc[0][nt][0], acc[0][nt][1], acc[0][nt][2], acc[0][nt][3],
                         afr[0][0], afr[0][1], afr[0][2], afr[0][3], b0, b1);
                mma_bf16(acc[1][nt][0], acc[1][nt][1], acc[1][nt][2], acc[1][nt][3],
                         afr[1][0], afr[1][1], afr[1][2], afr[1][3], b0, b1);
            }
        }

        if (more) {
            uint32_t* Aw = sA[p ^ 1];
            uint32_t* Bw = sB[p ^ 1];
            *(uint4*)&Aw[cr0 * SSTR + cs0 * 4] = pa0;
            *(uint4*)&Aw[cr1 * SSTR + cs0 * 4] = pa1;
            *(uint4*)&Bw[cr0 * SSTR + cs0 * 4] = pb0;
            *(uint4*)&Bw[cr1 * SSTR + cs0 * 4] = pb1;
        }
        __syncthreads();
        p ^= 1;
    }

    // ---------------- epilogue ----------------
#pragma unroll
    for (int mt = 0; mt < 2; mt++) {
        const int r0 = rowBase + warp_m * 32 + mt * 16 + g;
#pragma unroll
        for (int nt = 0; nt < 8; nt++) {
            const int c = colBase + warp_n * 64 + nt * 8 + 2 * t;
            const float bs0 = bias[c], bs1 = bias[c + 1];
            float x0 = acc[mt][nt][0] + bs0;
            float x1 = acc[mt][nt][1] + bs1;
            float x2 = acc[mt][nt][2] + bs0;
            float x3 = acc[mt][nt][3] + bs1;
            if (relu) {
                x0 = fmaxf(x0, 0.0f); x1 = fmaxf(x1, 0.0f);
                x2 = fmaxf(x2, 0.0f); x3 = fmaxf(x3, 0.0f);
            }
            if (mode == 0) {
                float2 v0 = { x0, x1 };
                float2 v1 = { x2, x3 };
                *(float2*)(Cf + (size_t)r0 * N + c) = v0;
                *(float2*)(Cf + (size_t)(r0 + 8) * N + c) = v1;
            } else {
                // write [hi | lo], row stride 2N
                __nv_bfloat16 h0, l0, h1, l1, h2, l2, h3, l3;
                bf16_split(x0, h0, l0); bf16_split(x1, h1, l1);
                bf16_split(x2, h2, l2); bf16_split(x3, h3, l3);
                const unsigned hu0 = bf16x2_u32(h0, h1), lu0 = bf16x2_u32(l0, l1);
                const unsigned hu1 = bf16x2_u32(h2, h3), lu1 = bf16x2_u32(l2, l3);
                size_t b0 = (size_t)r0 * (2 * N) + c;
                size_t b1 = (size_t)(r0 + 8) * (2 * N) + c;
                *(unsigned*)(Csp + b0)     = hu0;
                *(unsigned*)(Csp + b0 + N) = lu0;
                *(unsigned*)(Csp + b1)     = hu1;
                *(unsigned*)(Csp + b1 + N) = lu1;
            }
        }
    }
}

// ---------------- prep: src_features -> A2_sem [8192][1024] = [hi|lo] -----------
__global__ void prep_a_sem_kernel(const float* __restrict__ feat)
{
    const int m = blockIdx.x;
    const int t = threadIdx.x;                 // 0..127, cols 4t..4t+3
    char* row = (char*)(g_a_sem + (size_t)m * K2_SEM);
    const float4 v = ((const float4*)(feat + (size_t)m * CF))[t];
    __nv_bfloat16 h[4], l[4];
    bf16_split(v.x, h[0], l[0]);
    bf16_split(v.y, h[1], l[1]);
    bf16_split(v.z, h[2], l[2]);
    bf16_split(v.w, h[3], l[3]);
    ull hu = ((ull)bf16x2_u32(h[2], h[3]) << 32) | bf16x2_u32(h[0], h[1]);
    ull lu = ((ull)bf16x2_u32(l[2], l[3]) << 32) | bf16x2_u32(l[0], l[1]);
    *(ull*)(row + 8 * t)            = hu;
    *(ull*)(row + 2 * CF + 8 * t)   = lu;      // lo half at col 512
}

// ---------------- prep: W [K][N] -> B2 [N][2*Kpad] = [hi|lo], zero pad ----------
__global__ void prep_b_kernel(const float* __restrict__ W,
                              __nv_bfloat16* __restrict__ out,
                              int K, int Kpad, int N)
{
    const int n = blockIdx.x;
    __nv_bfloat16* row = out + (size_t)n * (2 * Kpad);
    for (int j = threadIdx.x; j < 2 * Kpad; j += 128) {
        __nv_bfloat16 r = __float2bfloat16(0.0f);
        int half = (j >= Kpad);
        int k = j - half * Kpad;
        if (k < K) {
            __nv_bfloat16 h, l;
            bf16_split(W[(size_t)k * N + n], h, l);
            r = half ? l : h;
        }
        row[j] = r;
    }
}

// ---------------- small SIMT GEMM (N=20 logits) --------------------------------
#define BM 64
#define BN 64
#define BK 16
__global__ void gemm_bias_act_kernel(const float* __restrict__ A,
                                     const float* __restrict__ B,
                                     const float* __restrict__ bias,
                                     float* __restrict__ C,
                                     int M, int N, int K, int relu)
{
    __shared__ float As[BK][BM + 1];
    __shared__ float Bs[BK][BN];
    const int tx = threadIdx.x, ty = threadIdx.y;
    const int tid = ty * 16 + tx;
    const int rowBase = blockIdx.y * BM, colBase = blockIdx.x * BN;
    float acc[4][4];
#pragma unroll
    for (int i = 0; i < 4; i++)
#pragma unroll
        for (int j = 0; j < 4; j++) acc[i][j] = 0.0f;
    const int ar = tid / 16, ac = tid % 16, bn = tid % 64, bk = tid / 64;
    for (int kt = 0; kt < K; kt += BK) {
#pragma unroll
        for (int j = 0; j < 4; j++) {
            int r = ar + j * 16, gr = rowBase + r, gc = kt + ac;
            As[ac][r] = (gc < K) ? A[(size_t)gr * K + gc] : 0.0f;
        }
#pragma unroll
        for (int j = 0; j < 4; j++) {
            int k = bk + j * 4, gk = kt + k, gn = colBase + bn;
            Bs[k][bn] = (gk < K && gn < N) ? B[(size_t)gk * N + gn] : 0.0f;
        }
        __syncthreads();
#pragma unroll
        for (int kk = 0; kk < BK; kk++) {
            float a[4], b[4];
#pragma unroll
            for (int i = 0; i < 4; i++) a[i] = As[kk][ty * 4 + i];
#pragma unroll
            for (int j = 0; j < 4; j++) b[j] = Bs[kk][tx * 4 + j];
#pragma unroll
            for (int i = 0; i < 4; i++)
#pragma unroll
                for (int j = 0; j < 4; j++)
                    acc[i][j] = fmaf(a[i], b[j], acc[i][j]);
        }
        __syncthreads();
    }
#pragma unroll
    for (int i = 0; i < 4; i++) {
        int gr = rowBase + ty * 4 + i;
#pragma unroll
        for (int j = 0; j < 4; j++) {
            int gc = colBase + tx * 4 + j;
            if (gc < N) {
                float v = acc[i][j] + bias[gc];
                if (relu) v = fmaxf(v, 0.0f);
                C[(size_t)gr * N + gc] = v;
            }
        }
    }
}

// ---------------- KNN: two-phase split-source ----------------------------------
#define KH        2048
#define KNN_TPW   4
#define KNN_TGTPB 32

__device__ __forceinline__ ull knn_packkey(float r, int j) {
    unsigned u = __float_as_uint(r);
    u = (u & 0x80000000u) ? ~u : (u | 0x80000000u);
    return ((ull)u << 32) | (unsigned)j;
}
__device__ __forceinline__ float knn_unpackr(ull k) {
    unsigned u = (unsigned)(k >> 32);
    u = (u & 0x80000000u) ? (u & 0x7fffffffu) : ~u;
    return __uint_as_float(u);
}
__device__ __forceinline__ void knn_insert(ull& k0, ull& k1, ull& k2, ull k) {
    if (k < k2) {
        if (k < k1) {
            k2 = k1;
            if (k < k0) { k1 = k0; k0 = k; }
            else        { k1 = k; }
        } else k2 = k;
    }
}
__device__ __forceinline__ void knn_insert_f(float& d0, float& d1, float& d2,
                                             int& i0, int& i1, int& i2,
                                             float r, int j) {
    if (r < d2) {
        if (r < d1) {
            d2 = d1; i2 = i1;
            if (r < d0) { d1 = d0; i1 = i0; d0 = r; i0 = j; }
            else        { d1 = r; i1 = j; }
        } else { d2 = r; i2 = j; }
    }
}

__global__ __launch_bounds__(256)
void knn_part_kernel(const float* __restrict__ src, const float* __restrict__ tgt)
{
    __shared__ float sx[KH], sy[KH], sz[KH];   // 24 KB
    const int b = blockIdx.z;
    const int h = blockIdx.y;
    const int jbase = h * KH;
    const float* s = src + ((size_t)b * MSRC + jbase) * 3;
    for (int i = threadIdx.x; i < KH; i += 256) {
        sx[i] = s[3 * i + 0]; sy[i] = s[3 * i + 1]; sz[i] = s[3 * i + 2];
    }
    __syncthreads();

    const int warp = threadIdx.x >> 5, lane = threadIdx.x & 31;
    const int tbase = blockIdx.x * KNN_TGTPB + warp * KNN_TPW;

    float qx[KNN_TPW], qy[KNN_TPW], qz[KNN_TPW];
#pragma unroll
    for (int t = 0; t < KNN_TPW; t++) {
        const float* tp = tgt + ((size_t)b * NTGT + tbase + t) * 3;
        qx[t] = -2.0f * tp[0]; qy[t] = -2.0f * tp[1]; qz[t] = -2.0f * tp[2];
    }

    float d0[KNN_TPW], d1[KNN_TPW], d2[KNN_TPW];
    int   i0[KNN_TPW], i1[KNN_TPW], i2[KNN_TPW];
#pragma unroll
    for (int t = 0; t < KNN_TPW; t++) {
        d0[t] = d1[t] = d2[t] = 1e30f; i0[t] = i1[t] = i2[t] = 0;
    }

    for (int j = lane; j < KH; j += 64) {
        const int ja = j, jb = j + 32;
        const float xa = sx[ja], ya = sy[ja], za = sz[ja];
        const float xb = sx[jb], yb = sy[jb], zb = sz[jb];
        const float s2a = fmaf(xa, xa, fmaf(ya, ya, za * za));
        const float s2b = fmaf(xb, xb, fmaf(yb, yb, zb * zb));
        float ra[KNN_TPW], rb[KNN_TPW];
#pragma unroll
        for (int t = 0; t < KNN_TPW; t++)
            ra[t] = fmaf(xa, qx[t], fmaf(ya, qy[t], fmaf(za, qz[t], s2a)));
#pragma unroll
        for (int t = 0; t < KNN_TPW; t++)
            rb[t] = fmaf(xb, qx[t], fmaf(yb, qy[t], fmaf(zb, qz[t], s2b)));
#pragma unroll
        for (int t = 0; t < KNN_TPW; t++) {
            knn_insert_f(d0[t], d1[t], d2[t], i0[t], i1[t], i2[t], ra[t], ja);
            knn_insert_f(d0[t], d1[t], d2[t], i0[t], i1[t], i2[t], rb[t], jb);
        }
    }

#pragma unroll
    for (int t = 0; t < KNN_TPW; t++) {
        ull k0 = knn_packkey(d0[t], jbase + i0[t]);
        ull k1 = knn_packkey(d1[t], jbase + i1[t]);
        ull k2 = knn_packkey(d2[t], jbase + i2[t]);
#pragma unroll
        for (int off = 16; off; off >>= 1) {
            ull o0 = __shfl_xor_sync(0xffffffffu, k0, off);
            ull o1 = __shfl_xor_sync(0xffffffffu, k1, off);
            ull o2 = __shfl_xor_sync(0xffffffffu, k2, off);
            knn_insert(k0, k1, k2, o0);
            knn_insert(k0, k1, k2, o1);
            knn_insert(k0, k1, k2, o2);
        }
        if (lane == 0) {
            const size_t base = (((size_t)b * NTGT + tbase + t) * 2 + h) * KNN;
            g_knn_cand[base + 0] = k0;
            g_knn_cand[base + 1] = k1;
            g_knn_cand[base + 2] = k2;
        }
    }
}

__global__ void knn_merge_kernel(const float* __restrict__ tgt)
{
    const int row = blockIdx.x * 256 + threadIdx.x;
    if (row >= BATCH * NTGT) return;
    const ull* cand = g_knn_cand + (size_t)row * 2 * KNN;
    ull k0 = cand[0], k1 = cand[1], k2 = cand[2];
    knn_insert(k0, k1, k2, cand[3]);
    knn_insert(k0, k1, k2, cand[4]);
    knn_insert(k0, k1, k2, cand[5]);

    const float* tp = tgt + (size_t)row * 3;
    const float pn = fmaf(tp[0], tp[0], fmaf(tp[1], tp[1], tp[2] * tp[2]));

    const size_t base = (size_t)row * KNN;
    g_knn_idx[base + 0] = (int)(unsigned)k0;
    g_knn_idx[base + 1] = (int)(unsigned)k1;
    g_knn_idx[base + 2] = (int)(unsigned)k2;
    g_knn_d[base + 0] = sqrtf(fmaxf(knn_unpackr(k0) + pn, 0.0f));
    g_knn_d[base + 1] = sqrtf(fmaxf(knn_unpackr(k1) + pn, 0.0f));
    g_knn_d[base + 2] = sqrtf(fmaxf(knn_unpackr(k2) + pn, 0.0f));
}

// ---------------- gather + fuse -> A2_up1 [16384][1088] = [hi|lo] ---------------
__global__ void fuse_kernel(const float* __restrict__ feat,
                            const float* __restrict__ sem)
{
    const int row = blockIdx.x;
    const int b = row / NTGT;
    const size_t base = (size_t)row * KNN;

    const int i0 = g_knn_idx[base + 0];
    const int i1 = g_knn_idx[base + 1];
    const int i2 = g_knn_idx[base + 2];
    const float dd0 = g_knn_d[base + 0];
    const float dd1 = g_knn_d[base + 1];
    const float dd2 = g_knn_d[base + 2];

    const float mn = fminf(dd0, fminf(dd1, dd2));
    const float e0 = expf(mn - dd0);
    const float e1 = expf(mn - dd1);
    const float e2 = expf(mn - dd2);
    const float inv = 1.0f / (e0 + e1 + e2);
    const float w0 = e0 * inv, w1 = e1 * inv, w2 = e2 * inv;

    char* crow = (char*)(g_a_up1 + (size_t)row * K2_UP1);   // hi at col 0, lo at col 544
    const int t = threadIdx.x;              // 0..127

    {
        const float4* f0 = (const float4*)(feat + ((size_t)(b * MSRC + i0)) * CF);
        const float4* f1 = (const float4*)(feat + ((size_t)(b * MSRC + i1)) * CF);
        const float4* f2 = (const float4*)(feat + ((size_t)(b * MSRC + i2)) * CF);
        float4 a0 = f0[t], a1 = f1[t], a2 = f2[t];
        float v[4];
        v[0] = fmaf(w0, a0.x, fmaf(w1, a1.x, w2 * a2.x));
        v[1] = fmaf(w0, a0.y, fmaf(w1, a1.y, w2 * a2.y));
        v[2] = fmaf(w0, a0.z, fmaf(w1, a1.z, w2 * a2.z));
        v[3] = fmaf(w0, a0.w, fmaf(w1, a1.w, w2 * a2.w));
        __nv_bfloat16 h[4], l[4];
#pragma unroll
        for (int q = 0; q < 4; q++) bf16_split(v[q], h[q], l[q]);
        ull hu = ((ull)bf16x2_u32(h[2], h[3]) << 32) | bf16x2_u32(h[0], h[1]);
        ull lu = ((ull)bf16x2_u32(l[2], l[3]) << 32) | bf16x2_u32(l[0], l[1]);
        *(ull*)(crow + 8 * t)                 = hu;   // hi, cols 4t..4t+3
        *(ull*)(crow + 2 * KP_UP1 + 8 * t)    = lu;   // lo, cols 544+4t..
    }

    // pad zeros: cols 532..543 (hi) and 1076..1087 (lo)
    if (t >= 32 && t < 56) {
        int j = t - 32;
        int col = (j < 12) ? (532 + j) : (1076 + (j - 12));
        ((__nv_bfloat16*)crow)[col] = __float2bfloat16(0.0f);
    }

    // semantic softmax-mean -> cols 512..531 (hi) / 1056..1075 (lo)
    if (t < 32) {
        int idx[3] = { i0, i1, i2 };
        float accsem = 0.0f;
#pragma unroll
        for (int k = 0; k < 3; k++) {
            const float* srow = sem + ((size_t)(b * MSRC + idx[k])) * NCLS;
            float vv = (t < NCLS) ? srow[t] : -1e30f;
            float m = vv;
#pragma unroll
            for (int off = 16; off; off >>= 1)
                m = fmaxf(m, __shfl_xor_sync(0xffffffffu, m, off));
            float e = (t < NCLS) ? expf(vv - m) : 0.0f;
            float ssum = e;
#pragma unroll
            for (int off = 16; off; off >>= 1)
                ssum += __shfl_xor_sync(0xffffffffu, ssum, off);
            accsem += e / ssum;
        }
        if (t < NCLS) {
            float v = accsem * (1.0f / 3.0f);
            __nv_bfloat16 h, l;
            bf16_split(v, h, l);
            __nv_bfloat16* rw = (__nv_bfloat16*)crow;
            rw[512 + t] = h;
            rw[KP_UP1 + 512 + t] = l;
        }
    }
}

// ---------------- launch --------------------------------------------------------
extern "C" void kernel_launch(void* const* d_in, const int* in_sizes, int n_in,
                              void* d_out, int out_size)
{
    const float* src_points   = (const float*)d_in[0];
    const float* tgt_points   = (const float*)d_in[1];
    const float* src_features = (const float*)d_in[2];
    const float* w_sem1 = (const float*)d_in[3];
    const float* b_sem1 = (const float*)d_in[4];
    const float* w_sem2 = (const float*)d_in[5];
    const float* b_sem2 = (const float*)d_in[6];
    const float* w_up1  = (const float*)d_in[7];
    const float* b_up1  = (const float*)d_in[8];
    const float* w_up2  = (const float*)d_in[9];
    const float* b_up2  = (const float*)d_in[10];

    float* out = (float*)d_out;
    float* sem_out = out + (size_t)BATCH * NTGT * OUTC;

    void* p;
    cudaGetSymbolAddress(&p, g_sem_hidden); float* sem_hidden = (float*)p;
    cudaGetSymbolAddress(&p, g_a_sem);      __nv_bfloat16* a_sem  = (__nv_bfloat16*)p;
    cudaGetSymbolAddress(&p, g_b_sem1);     __nv_bfloat16* bp_sem = (__nv_bfloat16*)p;
    cudaGetSymbolAddress(&p, g_a_up1);      __nv_bfloat16* a_up1  = (__nv_bfloat16*)p;
    cudaGetSymbolAddress(&p, g_b_up1);      __nv_bfloat16* bp_up1 = (__nv_bfloat16*)p;
    cudaGetSymbolAddress(&p, g_a_up2);      __nv_bfloat16* a_up2  = (__nv_bfloat16*)p;
    cudaGetSymbolAddress(&p, g_b_up2);      __nv_bfloat16* bp_up2 = (__nv_bfloat16*)p;

    // launch order chosen so the fixed-index ncu capture (4th launch) lands on
    // gemm_mma_kernel (sem1) for next-round evidence.
    prep_b_kernel<<<H1, 128>>>(w_sem1, bp_sem, CF, KP_SEM, H1);          // 0
    prep_b_kernel<<<H2, 128>>>(w_up1, bp_up1, CIN, KP_UP1, H2);          // 1
    prep_a_sem_kernel<<<BATCH * MSRC, 128>>>(src_features);              // 2

    // 3) sem hidden = relu(feat @ w_sem1 + b1)  -> fp32 [8192][128]
    gemm_mma_kernel<<<dim3(BATCH * MSRC / 128, H1 / 128), 256>>>(
        a_sem, bp_sem, b_sem1, sem_hidden, nullptr, H1, CPT_SEM, K2_SEM, 1, 0);

    // 4) logits = hidden @ w_sem2 + b2 -> d_out tail [8192][20]
    gemm_bias_act_kernel<<<dim3(1, BATCH * MSRC / BM), dim3(16, 16)>>>(
        sem_hidden, w_sem2, b_sem2, sem_out, BATCH * MSRC, NCLS, H1, 0);

    // 5,6) 3-NN two-phase
    knn_part_kernel<<<dim3(NTGT / KNN_TGTPB, 2, BATCH), 256>>>(src_points, tgt_points);
    knn_merge_kernel<<<(BATCH * NTGT + 255) / 256, 256>>>(tgt_points);

    // 7) fuse -> A2_up1 [hi|lo]
    fuse_kernel<<<BATCH * NTGT, 128>>>(src_features, sem_out);

    // 8) prep B for up2 (needed only before step 10)
    prep_b_kernel<<<OUTC, 128>>>(w_up2, bp_up2, H2, KP_UP2, OUTC);

    // 9) up hidden = relu(combined @ w_up1 + b)  -> A2_up2 [hi|lo]
    gemm_mma_kernel<<<dim3(BATCH * NTGT / 128, H2 / 128), 256>>>(
        a_up1, bp_up1, b_up1, nullptr, a_up2, H2, CPT_UP1, K2_UP1, 1, 1);

    // 10) out = up_hidden @ w_up2 + b  -> fp32 [16384][512]
    gemm_mma_kernel<<<dim3(BATCH * NTGT / 128, OUTC / 128), 256>>>(
        a_up2, bp_up2, b_up2, out, nullptr, OUTC, CPT_UP2, K2_UP2, 0, 0);
}

// round 12
// speedup vs baseline: 1.8730x; 1.0512x over previous
#include <cuda_runtime.h>
#include <cuda_bf16.h>
#include <math.h>
#include <cstdint>

#define BATCH 2
#define MSRC  4096
#define NTGT  8192
#define CF    512
#define NCLS  20
#define OUTC  512
#define H1    128
#define H2    256
#define CIN   532
#define KNN   3

// Split storage: A2 = [hi | lo] (2*Kpad cols); GEMM remaps logical thirds
// (A: hi,hi,lo / B: hi,lo,hi) onto this storage chunk-by-chunk.
#define KP_SEM  512
#define KP_UP1  544
#define KP_UP2  256
#define K2_SEM  1024
#define K2_UP1  1088
#define K2_UP2  512
#define CPT_SEM 16
#define CPT_UP1 17
#define CPT_UP2 8

typedef unsigned long long ull;

// ---------------- scratch (static device globals; no allocation) ----------------
__device__ __align__(256) float         g_sem_hidden[BATCH * MSRC * H1];
__device__ __align__(256) int           g_knn_idx[BATCH * NTGT * KNN];
__device__ __align__(256) float         g_knn_d[BATCH * NTGT * KNN];
__device__ __align__(256) ull           g_knn_cand[BATCH * NTGT * 2 * KNN];
__device__ __align__(256) __nv_bfloat16 g_a_sem[(size_t)BATCH * MSRC * K2_SEM];
__device__ __align__(256) __nv_bfloat16 g_b_sem1[H1 * K2_SEM];
__device__ __align__(256) __nv_bfloat16 g_a_up1[(size_t)BATCH * NTGT * K2_UP1];
__device__ __align__(256) __nv_bfloat16 g_b_up1[H2 * K2_UP1];
__device__ __align__(256) __nv_bfloat16 g_a_up2[(size_t)BATCH * NTGT * K2_UP2];
__device__ __align__(256) __nv_bfloat16 g_b_up2[OUTC * K2_UP2];

// ---------------- helpers -------------------------------------------------------
__device__ __forceinline__ void bf16_split(float v, __nv_bfloat16& h, __nv_bfloat16& l) {
    h = __float2bfloat16(v);
    l = __float2bfloat16(v - __bfloat162float(h));
}
__device__ __forceinline__ unsigned bf16x2_u32(__nv_bfloat16 a, __nv_bfloat16 b) {
    __nv_bfloat162 t; t.x = a; t.y = b;
    return *(unsigned*)&t;
}
__device__ __forceinline__ void mma_bf16(float& d0, float& d1, float& d2, float& d3,
                                         uint32_t a0, uint32_t a1, uint32_t a2, uint32_t a3,
                                         uint32_t b0, uint32_t b1) {
    asm volatile(
        "mma.sync.aligned.m16n8k16.row.col.f32.bf16.bf16.f32 "
        "{%0,%1,%2,%3}, {%4,%5,%6,%7}, {%8,%9}, {%0,%1,%2,%3};"
        : "+f"(d0), "+f"(d1), "+f"(d2), "+f"(d3)
        : "r"(a0), "r"(a1), "r"(a2), "r"(a3), "r"(b0), "r"(b1));
}
__device__ __forceinline__ uint32_t smem_u32(const void* p) {
    uint32_t a;
    asm("{ .reg .u64 t; cvta.to.shared.u64 t, %1; cvt.u32.u64 %0, t; }"
        : "=r"(a) : "l"(p));
    return a;
}
__device__ __forceinline__ void cp_async16(uint32_t saddr, const void* gptr) {
    asm volatile("cp.async.cg.shared.global [%0], [%1], 16;"
                 :: "r"(saddr), "l"(gptr) : "memory");
}
#define CP_COMMIT() asm volatile("cp.async.commit_group;" ::: "memory")
#define CP_WAIT2()  asm volatile("cp.async.wait_group 2;" ::: "memory")

// chunk remap: logical chunk ch (of 3*CPT) -> stored chunk in [hi|lo]
__device__ __forceinline__ void remap_chunk(int ch, int CPT, int& a_ch, int& b_ch) {
    int c = ch;
    int t = 0;
    if (ch >= 2 * CPT)      { t = 2; c = ch - 2 * CPT; }
    else if (ch >= CPT)     { t = 1; c = ch - CPT; }
    a_ch = (t == 2) ? CPT + c : c;   // A thirds: hi, hi, lo
    b_ch = (t == 1) ? CPT + c : c;   // B thirds: hi, lo, hi
}

// ================= mma.sync split-bf16 GEMM, cp.async 4-stage ===================
// D[M x N] = sum over 3*CPT logical k32-chunks of A2/B2 (stored [hi|lo]).
// mode 0: write fp32 C.  mode 1: write split bf16 [M][2N] as (h | l).
#define SSTR 20                         // words per row (32 bf16 = 16 words + 4 pad)
#define STAGES 4
#define HALF_BYTES (128 * SSTR * 4)     // one operand per stage: 10240 B
#define STAGE_BYTES (2 * HALF_BYTES)    // A+B per stage: 20480 B
#define GEMM_SMEM (STAGES * STAGE_BYTES)

__global__ __launch_bounds__(256, 2)
void gemm_mma_kernel(const __nv_bfloat16* __restrict__ Ap,
                     const __nv_bfloat16* __restrict__ Bp,
                     const float* __restrict__ bias,
                     float* __restrict__ Cf,
                     __nv_bfloat16* __restrict__ Csp,
                     int N, int CPT, int Kstore, int relu, int mode)
{
    extern __shared__ __align__(16) char dsm[];
    const uint32_t sbase = smem_u32(dsm);

    const int tid = threadIdx.x;
    const int wid = tid >> 5;
    const int lane = tid & 31;
    const int g = lane >> 2;
    const int t = lane & 3;

    const int warp_m = wid & 3;
    const int warp_n = wid >> 2;

    const int rowBase = blockIdx.x * 128;
    const int colBase = blockIdx.y * 128;

    const int cr0 = tid >> 2, cs0 = tid & 3;
    const int cr1 = (tid + 256) >> 2;
    const size_t krow = (size_t)Kstore * 2;      // bytes per stored row

    const char* Agp  = (const char*)Ap + (size_t)(rowBase + cr0) * krow + cs0 * 16;
    const char* Agp1 = (const char*)Ap + (size_t)(rowBase + cr1) * krow + cs0 * 16;
    const char* Bgp  = (const char*)Bp + (size_t)(colBase + cr0) * krow + cs0 * 16;
    const char* Bgp1 = (const char*)Bp + (size_t)(colBase + cr1) * krow + cs0 * 16;

    const uint32_t sa0 = sbase + (cr0 * SSTR + cs0 * 4) * 4;
    const uint32_t sa1 = sbase + (cr1 * SSTR + cs0 * 4) * 4;
    const uint32_t sb0 = sa0 + HALF_BYTES;
    const uint32_t sb1 = sa1 + HALF_BYTES;

    float acc[2][8][4];
#pragma unroll
    for (int i = 0; i < 2; i++)
#pragma unroll
        for (int j = 0; j < 8; j++)
#pragma unroll
            for (int q = 0; q < 4; q++) acc[i][j][q] = 0.0f;

    const int chunks = 3 * CPT;

    // issue_load lambda-ish macro
#define ISSUE_LOAD(CH, STG) do { \
        int _ach, _bch; \
        remap_chunk((CH), CPT, _ach, _bch); \
        const size_t _ao = (size_t)_ach * 64; \
        const size_t _bo = (size_t)_bch * 64; \
        const uint32_t _ss = (STG) * STAGE_BYTES; \
        cp_async16(sa0 + _ss, Agp + _ao); \
        cp_async16(sa1 + _ss, Agp1 + _ao); \
        cp_async16(sb0 + _ss, Bgp + _bo); \
        cp_async16(sb1 + _ss, Bgp1 + _bo); \
    } while (0)

    // prologue: stages 0..2
#pragma unroll
    for (int s = 0; s < STAGES - 1; s++) {
        if (s < chunks) ISSUE_LOAD(s, s);
        CP_COMMIT();
    }

    for (int ch = 0; ch < chunks; ch++) {
        CP_WAIT2();
        __syncthreads();          // stage ch%4 visible to all; compute(ch-1) done by all

        const int nc = ch + STAGES - 1;
        if (nc < chunks) ISSUE_LOAD(nc, nc & (STAGES - 1));
        CP_COMMIT();

        const uint32_t* A_ = (const uint32_t*)(dsm + (ch & (STAGES - 1)) * STAGE_BYTES);
        const uint32_t* B_ = A_ + 128 * SSTR;
#pragma unroll
        for (int s = 0; s < 2; s++) {
            const int w0 = s * 8 + t;
            uint32_t afr[2][4];
#pragma unroll
            for (int mt = 0; mt < 2; mt++) {
                const int r = warp_m * 32 + mt * 16 + g;
                afr[mt][0] = A_[r * SSTR + w0];
                afr[mt][1] = A_[(r + 8) * SSTR + w0];
                afr[mt][2] = A_[r * SSTR + w0 + 4];
                afr[mt][3] = A_[(r + 8) * SSTR + w0 + 4];
            }
#pragma unroll
            for (int nt = 0; nt < 8; nt++) {
                const int n = warp_n * 64 + nt * 8 + g;
                const uint32_t b0 = B_[n * SSTR + w0];
                const uint32_t b1 = B_[n * SSTR + w0 + 4];
                mma_bf16(acc[0][nt][0], acc[0][nt][1], acc[0][nt][2], acc[0][nt][3],
                         afr[0][0], afr[0][1], afr[0][2], afr[0][3], b0, b1);
                mma_bf16(acc[1][nt][0], acc[1][nt][1], acc[1][nt][2], acc[1][nt][3],
                         afr[1][0], afr[1][1], afr[1][2], afr[1][3], b0, b1);
            }
        }
    }
#undef ISSUE_LOAD

    // ---------------- epilogue ----------------
#pragma unroll
    for (int mt = 0; mt < 2; mt++) {
        const int r0 = rowBase + warp_m * 32 + mt * 16 + g;
#pragma unroll
        for (int nt = 0; nt < 8; nt++) {
            const int c = colBase + warp_n * 64 + nt * 8 + 2 * t;
            const float bs0 = bias[c], bs1 = bias[c + 1];
            float x0 = acc[mt][nt][0] + bs0;
            float x1 = acc[mt][nt][1] + bs1;
            float x2 = acc[mt][nt][2] + bs0;
            float x3 = acc[mt][nt][3] + bs1;
            if (relu) {
                x0 = fmaxf(x0, 0.0f); x1 = fmaxf(x1, 0.0f);
                x2 = fmaxf(x2, 0.0f); x3 = fmaxf(x3, 0.0f);
            }
            if (mode == 0) {
                float2 v0 = { x0, x1 };
                float2 v1 = { x2, x3 };
                *(float2*)(Cf + (size_t)r0 * N + c) = v0;
                *(float2*)(Cf + (size_t)(r0 + 8) * N + c) = v1;
            } else {
                __nv_bfloat16 h0, l0, h1, l1, h2, l2, h3, l3;
                bf16_split(x0, h0, l0); bf16_split(x1, h1, l1);
                bf16_split(x2, h2, l2); bf16_split(x3, h3, l3);
                const unsigned hu0 = bf16x2_u32(h0, h1), lu0 = bf16x2_u32(l0, l1);
                const unsigned hu1 = bf16x2_u32(h2, h3), lu1 = bf16x2_u32(l2, l3);
                size_t b0 = (size_t)r0 * (2 * N) + c;
                size_t b1 = (size_t)(r0 + 8) * (2 * N) + c;
                *(unsigned*)(Csp + b0)     = hu0;
                *(unsigned*)(Csp + b0 + N) = lu0;
                *(unsigned*)(Csp + b1)     = hu1;
                *(unsigned*)(Csp + b1 + N) = lu1;
            }
        }
    }
}

// ---------------- prep: src_features -> A2_sem [8192][1024] = [hi|lo] -----------
__global__ void prep_a_sem_kernel(const float* __restrict__ feat)
{
    const int m = blockIdx.x;
    const int t = threadIdx.x;
    char* row = (char*)(g_a_sem + (size_t)m * K2_SEM);
    const float4 v = ((const float4*)(feat + (size_t)m * CF))[t];
    __nv_bfloat16 h[4], l[4];
    bf16_split(v.x, h[0], l[0]);
    bf16_split(v.y, h[1], l[1]);
    bf16_split(v.z, h[2], l[2]);
    bf16_split(v.w, h[3], l[3]);
    ull hu = ((ull)bf16x2_u32(h[2], h[3]) << 32) | bf16x2_u32(h[0], h[1]);
    ull lu = ((ull)bf16x2_u32(l[2], l[3]) << 32) | bf16x2_u32(l[0], l[1]);
    *(ull*)(row + 8 * t)            = hu;
    *(ull*)(row + 2 * CF + 8 * t)   = lu;
}

// ---------------- prep: W [K][N] -> B2 [N][2*Kpad] = [hi|lo], zero pad ----------
__global__ void prep_b_kernel(const float* __restrict__ W,
                              __nv_bfloat16* __restrict__ out,
                              int K, int Kpad, int N)
{
    const int n = blockIdx.x;
    __nv_bfloat16* row = out + (size_t)n * (2 * Kpad);
    for (int j = threadIdx.x; j < 2 * Kpad; j += 128) {
        __nv_bfloat16 r = __float2bfloat16(0.0f);
        int half = (j >= Kpad);
        int k = j - half * Kpad;
        if (k < K) {
            __nv_bfloat16 h, l;
            bf16_split(W[(size_t)k * N + n], h, l);
            r = half ? l : h;
        }
        row[j] = r;
    }
}

// ---------------- small SIMT GEMM (N=20 logits) --------------------------------
#define BM 64
#define BN 64
#define BK 16
__global__ void gemm_bias_act_kernel(const float* __restrict__ A,
                                     const float* __restrict__ B,
                                     const float* __restrict__ bias,
                                     float* __restrict__ C,
                                     int M, int N, int K, int relu)
{
    __shared__ float As[BK][BM + 1];
    __shared__ float Bs[BK][BN];
    const int tx = threadIdx.x, ty = threadIdx.y;
    const int tid = ty * 16 + tx;
    const int rowBase = blockIdx.y * BM, colBase = blockIdx.x * BN;
    float acc[4][4];
#pragma unroll
    for (int i = 0; i < 4; i++)
#pragma unroll
        for (int j = 0; j < 4; j++) acc[i][j] = 0.0f;
    const int ar = tid / 16, ac = tid % 16, bn = tid % 64, bk = tid / 64;
    for (int kt = 0; kt < K; kt += BK) {
#pragma unroll
        for (int j = 0; j < 4; j++) {
            int r = ar + j * 16, gr = rowBase + r, gc = kt + ac;
            As[ac][r] = (gc < K) ? A[(size_t)gr * K + gc] : 0.0f;
        }
#pragma unroll
        for (int j = 0; j < 4; j++) {
            int k = bk + j * 4, gk = kt + k, gn = colBase + bn;
            Bs[k][bn] = (gk < K && gn < N) ? B[(size_t)gk * N + gn] : 0.0f;
        }
        __syncthreads();
#pragma unroll
        for (int kk = 0; kk < BK; kk++) {
            float a[4], b[4];
#pragma unroll
            for (int i = 0; i < 4; i++) a[i] = As[kk][ty * 4 + i];
#pragma unroll
            for (int j = 0; j < 4; j++) b[j] = Bs[kk][tx * 4 + j];
#pragma unroll
            for (int i = 0; i < 4; i++)
#pragma unroll
                for (int j = 0; j < 4; j++)
                    acc[i][j] = fmaf(a[i], b[j], acc[i][j]);
        }
        __syncthreads();
    }
#pragma unroll
    for (int i = 0; i < 4; i++) {
        int gr = rowBase + ty * 4 + i;
#pragma unroll
        for (int j = 0; j < 4; j++) {
            int gc = colBase + tx * 4 + j;
            if (gc < N) {
                float v = acc[i][j] + bias[gc];
                if (relu) v = fmaxf(v, 0.0f);
                C[(size_t)gr * N + gc] = v;
            }
        }
    }
}

// ---------------- KNN: two-phase split-source ----------------------------------
#define KH        2048
#define KNN_TPW   4
#define KNN_TGTPB 32

__device__ __forceinline__ ull knn_packkey(float r, int j) {
    unsigned u = __float_as_uint(r);
    u = (u & 0x80000000u) ? ~u : (u | 0x80000000u);
    return ((ull)u << 32) | (unsigned)j;
}
__device__ __forceinline__ float knn_unpackr(ull k) {
    unsigned u = (unsigned)(k >> 32);
    u = (u & 0x80000000u) ? (u & 0x7fffffffu) : ~u;
    return __uint_as_float(u);
}
__device__ __forceinline__ void knn_insert(ull& k0, ull& k1, ull& k2, ull k) {
    if (k < k2) {
        if (k < k1) {
            k2 = k1;
            if (k < k0) { k1 = k0; k0 = k; }
            else        { k1 = k; }
        } else k2 = k;
    }
}
__device__ __forceinline__ void knn_insert_f(float& d0, float& d1, float& d2,
                                             int& i0, int& i1, int& i2,
                                             float r, int j) {
    if (r < d2) {
        if (r < d1) {
            d2 = d1; i2 = i1;
            if (r < d0) { d1 = d0; i1 = i0; d0 = r; i0 = j; }
            else        { d1 = r; i1 = j; }
        } else { d2 = r; i2 = j; }
    }
}

__global__ __launch_bounds__(256)
void knn_part_kernel(const float* __restrict__ src, const float* __restrict__ tgt)
{
    __shared__ float sx[KH], sy[KH], sz[KH];
    const int b = blockIdx.z;
    const int h = blockIdx.y;
    const int jbase = h * KH;
    const float* s = src + ((size_t)b * MSRC + jbase) * 3;
    for (int i = threadIdx.x; i < KH; i += 256) {
        sx[i] = s[3 * i + 0]; sy[i] = s[3 * i + 1]; sz[i] = s[3 * i + 2];
    }
    __syncthreads();

    const int warp = threadIdx.x >> 5, lane = threadIdx.x & 31;
    const int tbase = blockIdx.x * KNN_TGTPB + warp * KNN_TPW;

    float qx[KNN_TPW], qy[KNN_TPW], qz[KNN_TPW];
#pragma unroll
    for (int t = 0; t < KNN_TPW; t++) {
        const float* tp = tgt + ((size_t)b * NTGT + tbase + t) * 3;
        qx[t] = -2.0f * tp[0]; qy[t] = -2.0f * tp[1]; qz[t] = -2.0f * tp[2];
    }

    float d0[KNN_TPW], d1[KNN_TPW], d2[KNN_TPW];
    int   i0[KNN_TPW], i1[KNN_TPW], i2[KNN_TPW];
#pragma unroll
    for (int t = 0; t < KNN_TPW; t++) {
        d0[t] = d1[t] = d2[t] = 1e30f; i0[t] = i1[t] = i2[t] = 0;
    }

    for (int j = lane; j < KH; j += 64) {
        const int ja = j, jb = j + 32;
        const float xa = sx[ja], ya = sy[ja], za = sz[ja];
        const float xb = sx[jb], yb = sy[jb], zb = sz[jb];
        const float s2a = fmaf(xa, xa, fmaf(ya, ya, za * za));
        const float s2b = fmaf(xb, xb, fmaf(yb, yb, zb * zb));
        float ra[KNN_TPW], rb[KNN_TPW];
#pragma unroll
        for (int t = 0; t < KNN_TPW; t++)
            ra[t] = fmaf(xa, qx[t], fmaf(ya, qy[t], fmaf(za, qz[t], s2a)));
#pragma unroll
        for (int t = 0; t < KNN_TPW; t++)
            rb[t] = fmaf(xb, qx[t], fmaf(yb, qy[t], fmaf(zb, qz[t], s2b)));
#pragma unroll
        for (int t = 0; t < KNN_TPW; t++) {
            knn_insert_f(d0[t], d1[t], d2[t], i0[t], i1[t], i2[t], ra[t], ja);
            knn_insert_f(d0[t], d1[t], d2[t], i0[t], i1[t], i2[t], rb[t], jb);
        }
    }

#pragma unroll
    for (int t = 0; t < KNN_TPW; t++) {
        ull k0 = knn_packkey(d0[t], jbase + i0[t]);
        ull k1 = knn_packkey(d1[t], jbase + i1[t]);
        ull k2 = knn_packkey(d2[t], jbase + i2[t]);
#pragma unroll
        for (int off = 16; off; off >>= 1) {
            ull o0 = __shfl_xor_sync(0xffffffffu, k0, off);
            ull o1 = __shfl_xor_sync(0xffffffffu, k1, off);
            ull o2 = __shfl_xor_sync(0xffffffffu, k2, off);
            knn_insert(k0, k1, k2, o0);
            knn_insert(k0, k1, k2, o1);
            knn_insert(k0, k1, k2, o2);
        }
        if (lane == 0) {
            const size_t base = (((size_t)b * NTGT + tbase + t) * 2 + h) * KNN;
            g_knn_cand[base + 0] = k0;
            g_knn_cand[base + 1] = k1;
            g_knn_cand[base + 2] = k2;
        }
    }
}

__global__ void knn_merge_kernel(const float* __restrict__ tgt)
{
    const int row = blockIdx.x * 256 + threadIdx.x;
    if (row >= BATCH * NTGT) return;
    const ull* cand = g_knn_cand + (size_t)row * 2 * KNN;
    ull k0 = cand[0], k1 = cand[1], k2 = cand[2];
    knn_insert(k0, k1, k2, cand[3]);
    knn_insert(k0, k1, k2, cand[4]);
    knn_insert(k0, k1, k2, cand[5]);

    const float* tp = tgt + (size_t)row * 3;
    const float pn = fmaf(tp[0], tp[0], fmaf(tp[1], tp[1], tp[2] * tp[2]));

    const size_t base = (size_t)row * KNN;
    g_knn_idx[base + 0] = (int)(unsigned)k0;
    g_knn_idx[base + 1] = (int)(unsigned)k1;
    g_knn_idx[base + 2] = (int)(unsigned)k2;
    g_knn_d[base + 0] = sqrtf(fmaxf(knn_unpackr(k0) + pn, 0.0f));
    g_knn_d[base + 1] = sqrtf(fmaxf(knn_unpackr(k1) + pn, 0.0f));
    g_knn_d[base + 2] = sqrtf(fmaxf(knn_unpackr(k2) + pn, 0.0f));
}

// ---------------- gather + fuse -> A2_up1 [16384][1088] = [hi|lo] ---------------
__global__ void fuse_kernel(const float* __restrict__ feat,
                            const float* __restrict__ sem)
{
    const int row = blockIdx.x;
    const int b = row / NTGT;
    const size_t base = (size_t)row * KNN;

    const int i0 = g_knn_idx[base + 0];
    const int i1 = g_knn_idx[base + 1];
    const int i2 = g_knn_idx[base + 2];
    const float dd0 = g_knn_d[base + 0];
    const float dd1 = g_knn_d[base + 1];
    const float dd2 = g_knn_d[base + 2];

    const float mn = fminf(dd0, fminf(dd1, dd2));
    const float e0 = expf(mn - dd0);
    const float e1 = expf(mn - dd1);
    const float e2 = expf(mn - dd2);
    const float inv = 1.0f / (e0 + e1 + e2);
    const float w0 = e0 * inv, w1 = e1 * inv, w2 = e2 * inv;

    char* crow = (char*)(g_a_up1 + (size_t)row * K2_UP1);
    const int t = threadIdx.x;

    {
        const float4* f0 = (const float4*)(feat + ((size_t)(b * MSRC + i0)) * CF);
        const float4* f1 = (const float4*)(feat + ((size_t)(b * MSRC + i1)) * CF);
        const float4* f2 = (const float4*)(feat + ((size_t)(b * MSRC + i2)) * CF);
        float4 a0 = f0[t], a1 = f1[t], a2 = f2[t];
        float v[4];
        v[0] = fmaf(w0, a0.x, fmaf(w1, a1.x, w2 * a2.x));
        v[1] = fmaf(w0, a0.y, fmaf(w1, a1.y, w2 * a2.y));
        v[2] = fmaf(w0, a0.z, fmaf(w1, a1.z, w2 * a2.z));
        v[3] = fmaf(w0, a0.w, fmaf(w1, a1.w, w2 * a2.w));
        __nv_bfloat16 h[4], l[4];
#pragma unroll
        for (int q = 0; q < 4; q++) bf16_split(v[q], h[q], l[q]);
        ull hu = ((ull)bf16x2_u32(h[2], h[3]) << 32) | bf16x2_u32(h[0], h[1]);
        ull lu = ((ull)bf16x2_u32(l[2], l[3]) << 32) | bf16x2_u32(l[0], l[1]);
        *(ull*)(crow + 8 * t)                 = hu;
        *(ull*)(crow + 2 * KP_UP1 + 8 * t)    = lu;
    }

    if (t >= 32 && t < 56) {
        int j = t - 32;
        int col = (j < 12) ? (532 + j) : (1076 + (j - 12));
        ((__nv_bfloat16*)crow)[col] = __float2bfloat16(0.0f);
    }

    if (t < 32) {
        int idx[3] = { i0, i1, i2 };
        float accsem = 0.0f;
#pragma unroll
        for (int k = 0; k < 3; k++) {
            const float* srow = sem + ((size_t)(b * MSRC + idx[k])) * NCLS;
            float vv = (t < NCLS) ? srow[t] : -1e30f;
            float m = vv;
#pragma unroll
            for (int off = 16; off; off >>= 1)
                m = fmaxf(m, __shfl_xor_sync(0xffffffffu, m, off));
            float e = (t < NCLS) ? expf(vv - m) : 0.0f;
            float ssum = e;
#pragma unroll
            for (int off = 16; off; off >>= 1)
                ssum += __shfl_xor_sync(0xffffffffu, ssum, off);
            accsem += e / ssum;
        }
        if (t < NCLS) {
            float v = accsem * (1.0f / 3.0f);
            __nv_bfloat16 h, l;
            bf16_split(v, h, l);
            __nv_bfloat16* rw = (__nv_bfloat16*)crow;
            rw[512 + t] = h;
            rw[KP_UP1 + 512 + t] = l;
        }
    }
}

// ---------------- launch --------------------------------------------------------
extern "C" void kernel_launch(void* const* d_in, const int* in_sizes, int n_in,
                              void* d_out, int out_size)
{
    const float* src_points   = (const float*)d_in[0];
    const float* tgt_points   = (const float*)d_in[1];
    const float* src_features = (const float*)d_in[2];
    const float* w_sem1 = (const float*)d_in[3];
    const float* b_sem1 = (const float*)d_in[4];
    const float* w_sem2 = (const float*)d_in[5];
    const float* b_sem2 = (const float*)d_in[6];
    const float* w_up1  = (const float*)d_in[7];
    const float* b_up1  = (const float*)d_in[8];
    const float* w_up2  = (const float*)d_in[9];
    const float* b_up2  = (const float*)d_in[10];

    float* out = (float*)d_out;
    float* sem_out = out + (size_t)BATCH * NTGT * OUTC;

    void* p;
    cudaGetSymbolAddress(&p, g_sem_hidden); float* sem_hidden = (float*)p;
    cudaGetSymbolAddress(&p, g_a_sem);      __nv_bfloat16* a_sem  = (__nv_bfloat16*)p;
    cudaGetSymbolAddress(&p, g_b_sem1);     __nv_bfloat16* bp_sem = (__nv_bfloat16*)p;
    cudaGetSymbolAddress(&p, g_a_up1);      __nv_bfloat16* a_up1  = (__nv_bfloat16*)p;
    cudaGetSymbolAddress(&p, g_b_up1);      __nv_bfloat16* bp_up1 = (__nv_bfloat16*)p;
    cudaGetSymbolAddress(&p, g_a_up2);      __nv_bfloat16* a_up2  = (__nv_bfloat16*)p;
    cudaGetSymbolAddress(&p, g_b_up2);      __nv_bfloat16* bp_up2 = (__nv_bfloat16*)p;

    cudaFuncSetAttribute(gemm_mma_kernel,
                         cudaFuncAttributeMaxDynamicSharedMemorySize, GEMM_SMEM);

    // same launch order: capture slot lands on gemm_mma (sem1) again
    prep_b_kernel<<<H1, 128>>>(w_sem1, bp_sem, CF, KP_SEM, H1);          // 0
    prep_b_kernel<<<H2, 128>>>(w_up1, bp_up1, CIN, KP_UP1, H2);          // 1
    prep_a_sem_kernel<<<BATCH * MSRC, 128>>>(src_features);              // 2

    // 3) sem hidden = relu(feat @ w_sem1 + b1)  -> fp32 [8192][128]
    gemm_mma_kernel<<<dim3(BATCH * MSRC / 128, H1 / 128), 256, GEMM_SMEM>>>(
        a_sem, bp_sem, b_sem1, sem_hidden, nullptr, H1, CPT_SEM, K2_SEM, 1, 0);

    // 4) logits = hidden @ w_sem2 + b2 -> d_out tail [8192][20]
    gemm_bias_act_kernel<<<dim3(1, BATCH * MSRC / BM), dim3(16, 16)>>>(
        sem_hidden, w_sem2, b_sem2, sem_out, BATCH * MSRC, NCLS, H1, 0);

    // 5,6) 3-NN two-phase
    knn_part_kernel<<<dim3(NTGT / KNN_TGTPB, 2, BATCH), 256>>>(src_points, tgt_points);
    knn_merge_kernel<<<(BATCH * NTGT + 255) / 256, 256>>>(tgt_points);

    // 7) fuse -> A2_up1 [hi|lo]
    fuse_kernel<<<BATCH * NTGT, 128>>>(src_features, sem_out);

    // 8) prep B for up2
    prep_b_kernel<<<OUTC, 128>>>(w_up2, bp_up2, H2, KP_UP2, OUTC);

    // 9) up hidden = relu(combined @ w_up1 + b)  -> A2_up2 [hi|lo]
    gemm_mma_kernel<<<dim3(BATCH * NTGT / 128, H2 / 128), 256, GEMM_SMEM>>>(
        a_up1, bp_up1, b_up1, nullptr, a_up2, H2, CPT_UP1, K2_UP1, 1, 1);

    // 10) out = up_hidden @ w_up2 + b  -> fp32 [16384][512]
    gemm_mma_kernel<<<dim3(BATCH * NTGT / 128, OUTC / 128), 256, GEMM_SMEM>>>(
        a_up2, bp_up2, b_up2, out, nullptr, OUTC, CPT_UP2, K2_UP2, 0, 0);
}